// round 13
// baseline (speedup 1.0000x reference)
#include <cuda_runtime.h>
#include <cuda.h>
#include <cuda_fp16.h>
#include <math.h>
#include <stdint.h>

// Problem dims (fixed by reference)
#define S_    2048
#define B_    2
#define H_    1024
#define NH_   16
#define HD_   64
#define ROWS  (S_*B_)      // 4096
#define H3    (3*H_)       // 3072
#define H4    (4*H_)       // 4096
#define BHN   (B_*NH_)     // 32

// ---------------- scratch (no allocations allowed) ----------------
__device__ float   g_x1   [ROWS*(size_t)H_];   // fp32 post-attn residual
__device__ __half  g_a    [ROWS*(size_t)H_];   // activation (single fp16)
__device__ __half  g_m    [ROWS*(size_t)H4];   // mid (fc2 input)
__device__ __half  g_wqkv [H3*(size_t)H_];
__device__ __half  g_wproj[H_*(size_t)H_];
__device__ __half  g_wfc1 [H4*(size_t)H_];
__device__ __half  g_wfc2 [H_*(size_t)H4];
// Q,K,V single fp16, layout [(b*16+h), s, d]
__device__ __half  g_q [BHN*(size_t)S_*HD_];
__device__ __half  g_k [BHN*(size_t)S_*HD_];
__device__ __half  g_v [BHN*(size_t)S_*HD_];

// ---------------- PTX helpers ----------------
__device__ __forceinline__ uint32_t smem_u32(const void* p) {
    uint32_t a;
    asm("{ .reg .u64 t; cvta.to.shared.u64 t, %1; cvt.u32.u64 %0, t; }" : "=r"(a) : "l"(p));
    return a;
}

#define MBARRIER_INIT(addr, cnt) \
    asm volatile("mbarrier.init.shared.b64 [%0], %1;" :: "r"(addr), "r"(cnt) : "memory")
#define MBARRIER_ARRIVE(addr) \
    asm volatile("mbarrier.arrive.shared.b64 _, [%0];" :: "r"(addr) : "memory")
#define MBARRIER_EXPECT_TX(addr, bytes) \
    asm volatile("mbarrier.arrive.expect_tx.shared.b64 _, [%0], %1;" :: "r"(addr), "r"(bytes) : "memory")

#define MBARRIER_WAIT_PARITY(addr, phase) do { \
    uint32_t _m = (addr); uint32_t _p = (phase); uint32_t _d; \
    asm volatile("{\n\t.reg .pred p;\n\t" \
        "mbarrier.try_wait.parity.acquire.cta.shared::cta.b64 p, [%1], %2;\n\t" \
        "selp.b32 %0, 1, 0, p;\n\t}" : "=r"(_d) : "r"(_m), "r"(_p) : "memory"); \
    if (!_d) { \
        asm volatile("{\n\t.reg .pred P1;\n\t" \
            "WL_%=:\n\t" \
            "mbarrier.try_wait.parity.acquire.cta.shared::cta.b64 P1, [%0], %1, 0x989680;\n\t" \
            "@P1 bra.uni WD_%=;\n\t" \
            "bra.uni WL_%=;\n\t" \
            "WD_%=:\n\t}" :: "r"(_m), "r"(_p) : "memory"); \
    } \
} while (0)

#define MBARRIER_WAIT_PARITY_RELAXED(addr, phase) do { \
    uint32_t _m = (addr); uint32_t _p = (phase); uint32_t _d; \
    asm volatile("{\n\t.reg .pred p;\n\t" \
        "mbarrier.try_wait.parity.relaxed.cta.shared::cta.b64 p, [%1], %2, 0x989680;\n\t" \
        "selp.b32 %0, 1, 0, p;\n\t}" : "=r"(_d) : "r"(_m), "r"(_p) : "memory"); \
    if (!_d) { \
        asm volatile("{\n\t.reg .pred P1;\n\t" \
            "WL_%=:\n\t" \
            "mbarrier.try_wait.parity.relaxed.cta.shared::cta.b64 P1, [%0], %1, 0x989680;\n\t" \
            "@P1 bra.uni WD_%=;\n\t" \
            "bra.uni WL_%=;\n\t" \
            "WD_%=:\n\t}" :: "r"(_m), "r"(_p) : "memory"); \
    } \
} while (0)

__device__ __forceinline__ void tma2d(uint32_t dst, const void* map, int x, int y, uint32_t mbar) {
    asm volatile("cp.async.bulk.tensor.2d.shared::cta.global.tile.mbarrier::complete_tx::bytes "
                 "[%0], [%1, {%2, %3}], [%4];"
                 :: "r"(dst), "l"(map), "r"(x), "r"(y), "r"(mbar) : "memory");
}

__device__ __forceinline__ void ldsm4(uint32_t* r, uint32_t addr) {
    asm volatile("ldmatrix.sync.aligned.m8n8.x4.shared.b16 {%0,%1,%2,%3}, [%4];"
                 : "=r"(r[0]), "=r"(r[1]), "=r"(r[2]), "=r"(r[3]) : "r"(addr));
}
__device__ __forceinline__ void ldsm4t(uint32_t* r, uint32_t addr) {
    asm volatile("ldmatrix.sync.aligned.m8n8.x4.trans.shared.b16 {%0,%1,%2,%3}, [%4];"
                 : "=r"(r[0]), "=r"(r[1]), "=r"(r[2]), "=r"(r[3]) : "r"(addr));
}

__device__ __forceinline__ void mma16816h(float* d, const uint32_t* a, const uint32_t* b) {
    asm volatile("mma.sync.aligned.m16n8k16.row.col.f32.f16.f16.f32 "
                 "{%0,%1,%2,%3}, {%4,%5,%6,%7}, {%8,%9}, {%0,%1,%2,%3};"
                 : "+f"(d[0]), "+f"(d[1]), "+f"(d[2]), "+f"(d[3])
                 : "r"(a[0]), "r"(a[1]), "r"(a[2]), "r"(a[3]), "r"(b[0]), "r"(b[1]));
}

__device__ __forceinline__ void cp16(uint32_t dst, const void* src) {
    asm volatile("cp.async.cg.shared.global [%0], [%1], 16;" :: "r"(dst), "l"(src) : "memory");
}
#define CP_COMMIT() asm volatile("cp.async.commit_group;" ::: "memory")
#define CP_WAIT(n)  asm volatile("cp.async.wait_group %0;" :: "n"(n) : "memory")

__device__ __forceinline__ float gelu_tanh(float u) {
    float c = 0.7978845608028654f * (u + 0.044715f * u * u * u);
    return 0.5f * u * (1.f + tanhf(c));
}

// ---------------- LayerNorm row body (fp16 out) ----------------
__device__ __forceinline__ void ln_row(const float* __restrict__ x, const float* __restrict__ w,
                                       const float* __restrict__ b, __half* __restrict__ y, int row)
{
    const int t = threadIdx.x;
    float4 v = ((const float4*)(x + (size_t)row * H_))[t];
    float s  = v.x + v.y + v.z + v.w;
    float sq = v.x*v.x + v.y*v.y + v.z*v.z + v.w*v.w;
    #pragma unroll
    for (int o = 16; o > 0; o >>= 1) {
        s  += __shfl_xor_sync(0xffffffffu, s,  o);
        sq += __shfl_xor_sync(0xffffffffu, sq, o);
    }
    __shared__ float ss[8], ssq[8];
    const int wid = t >> 5, lid = t & 31;
    if (lid == 0) { ss[wid] = s; ssq[wid] = sq; }
    __syncthreads();
    if (wid == 0) {
        float s2 = (lid < 8) ? ss[lid]  : 0.f;
        float q2 = (lid < 8) ? ssq[lid] : 0.f;
        #pragma unroll
        for (int o = 4; o > 0; o >>= 1) {
            s2 += __shfl_xor_sync(0xffffffffu, s2, o);
            q2 += __shfl_xor_sync(0xffffffffu, q2, o);
        }
        if (lid == 0) { ss[0] = s2; ssq[0] = q2; }
    }
    __syncthreads();
    const float mean = ss[0] * (1.f / H_);
    const float var  = ssq[0] * (1.f / H_) - mean * mean;
    const float rstd = rsqrtf(var + 1e-5f);
    float4 wv = ((const float4*)w)[t];
    float4 bv = ((const float4*)b)[t];
    float y0 = (v.x - mean) * rstd * wv.x + bv.x;
    float y1 = (v.y - mean) * rstd * wv.y + bv.y;
    float y2 = (v.z - mean) * rstd * wv.z + bv.z;
    float y3 = (v.w - mean) * rstd * wv.w + bv.w;
    __half2* yp = (__half2*)(y + (size_t)row * H_);
    yp[t*2]   = __floats2half2_rn(y0, y1);
    yp[t*2+1] = __floats2half2_rn(y2, y3);
}

__global__ void __launch_bounds__(256)
ln_h(const float* __restrict__ x, const float* __restrict__ w, const float* __restrict__ b,
     __half* __restrict__ y)
{
    ln_row(x, w, b, y, blockIdx.x);
}

// ---------------- fused: ln1 + all-weight fp32->fp16 convert ----------------
#define N4_QKV  (H3*H_/4)
#define N4_PROJ (H_*H_/4)
#define N4_FC1  (H4*H_/4)
#define N4_FC2  (H_*H4/4)
#define N4_ALL  (N4_QKV + N4_PROJ + N4_FC1 + N4_FC2)

__global__ void __launch_bounds__(256)
fused_prep(const float* __restrict__ x, const float* __restrict__ ln1w, const float* __restrict__ ln1b,
           __half* __restrict__ a16,
           const float* __restrict__ w0, const float* __restrict__ w1,
           const float* __restrict__ w2, const float* __restrict__ w3,
           __half* __restrict__ o0, __half* __restrict__ o1,
           __half* __restrict__ o2, __half* __restrict__ o3)
{
    if (blockIdx.x < ROWS) { ln_row(x, ln1w, ln1b, a16, blockIdx.x); return; }
    int i = (blockIdx.x - ROWS) * 256 + threadIdx.x;
    if (i >= N4_ALL) return;
    const float* s; __half* d; int k = i;
    if (k < N4_QKV)                    { s = w0; d = o0; }
    else if ((k -= N4_QKV)  < N4_PROJ) { s = w1; d = o1; }
    else if ((k -= N4_PROJ) < N4_FC1)  { s = w2; d = o2; }
    else { k -= N4_FC1;                  s = w3; d = o3; }
    float4 v = ((const float4*)s)[k];
    ((__half2*)d)[2*k]   = __floats2half2_rn(v.x, v.y);
    ((__half2*)d)[2*k+1] = __floats2half2_rn(v.z, v.w);
}

// ---------------- fp16 1-term GEMM (non-persistent, frozen) ----------------
// MODE 0: +bias -> scatter Q (scaled log2e/8), K, V (single fp16)
// MODE 1: gelu(+bias) -> fp16 C16
// MODE 2: +bias+resid -> fp32 C
static constexpr int SMEM_BYTES = 3*32768 + 1024;

template<int MODE>
__global__ void __launch_bounds__(288, 2)
gemm_tc(const __grid_constant__ CUtensorMap mA,
        const __grid_constant__ CUtensorMap mB,
        const float* __restrict__ bias, const float* __restrict__ resid,
        float* __restrict__ C, __half* __restrict__ C16,
        __half* __restrict__ qq, __half* __restrict__ kk, __half* __restrict__ vv,
        int N, int nc)
{
    extern __shared__ char smem[];
    const uint32_t sb  = smem_u32(smem);
    const uint32_t st0 = (sb + 64 + 1023) & ~1023u;
    const int tid = threadIdx.x;

    if (tid == 0) {
        #pragma unroll
        for (int i = 0; i < 3; i++) {
            MBARRIER_INIT(sb + 8*i, 1);
            MBARRIER_INIT(sb + 24 + 8*i, 8);
        }
    }
    __syncthreads();

    const int bx = blockIdx.x, by = blockIdx.y;

    if (tid >= 256) {
        if (tid == 256) {
            for (int c = 0; c < nc; c++) {
                const int s = c % 3, r = c / 3;
                const uint32_t stg = st0 + s * 32768;
                if (r > 0) MBARRIER_WAIT_PARITY_RELAXED(sb + 24 + 8*s, (r - 1) & 1);
                MBARRIER_EXPECT_TX(sb + 8*s, 32768u);
                const int kx = c * 64;
                tma2d(stg,         &mA, kx, by * 128, sb + 8*s);
                tma2d(stg + 16384, &mB, kx, bx * 128, sb + 8*s);
            }
        }
        return;
    }

    const int lane = tid & 31;
    const int wm = (tid >> 5) >> 1;
    const int wn = (tid >> 5) & 1;

    const int arow0 = wm*32 + (lane & 15);
    const int acx   = lane >> 4;
    const int brow0 = wn*64 + (lane & 7) + ((lane >> 4) << 3);
    const int bcx   = (lane >> 3) & 1;

    float acc[2][8][4];
    #pragma unroll
    for (int i = 0; i < 2; i++)
        #pragma unroll
        for (int j = 0; j < 8; j++)
            #pragma unroll
            for (int q = 0; q < 4; q++) acc[i][j][q] = 0.f;

    for (int c = 0; c < nc; c++) {
        const int s = c % 3, r = c / 3;
        const uint32_t stg = st0 + s * 32768;
        MBARRIER_WAIT_PARITY(sb + 8*s, r & 1);

        #pragma unroll
        for (int ks = 0; ks < 4; ks++) {
            uint32_t af[2][4], bf[4][4];
            #pragma unroll
            for (int i = 0; i < 2; i++) {
                const int row = arow0 + i*16;
                const int cc  = 2*ks + acx;
                const uint32_t off = row*128 + (((uint32_t)(cc ^ (row & 7))) << 4);
                ldsm4(af[i], stg + off);
            }
            #pragma unroll
            for (int jt = 0; jt < 4; jt++) {
                const int row = brow0 + jt*16;
                const int cc  = 2*ks + bcx;
                const uint32_t off = row*128 + (((uint32_t)(cc ^ (row & 7))) << 4);
                ldsm4(bf[jt], stg + 16384 + off);
            }
            #pragma unroll
            for (int i = 0; i < 2; i++)
                #pragma unroll
                for (int j = 0; j < 8; j++)
                    mma16816h(acc[i][j], af[i], &bf[j>>1][(j&1)*2]);
        }
        if (lane == 0) MBARRIER_ARRIVE(sb + 24 + 8*s);
    }

    // ---- epilogue ----
    const int rbase = by*128 + wm*32 + (lane >> 2);
    const int cbase = bx*128 + wn*64 + (lane & 3)*2;
    #pragma unroll
    for (int j = 0; j < 8; j++) {
        const int col = cbase + j*8;
        const float bx0 = bias[col], bx1 = bias[col + 1];
        #pragma unroll
        for (int i = 0; i < 2; i++) {
            #pragma unroll
            for (int half = 0; half < 2; half++) {
                const int rowg = rbase + i*16 + half*8;
                float v0 = acc[i][j][half*2 + 0] + bx0;
                float v1 = acc[i][j][half*2 + 1] + bx1;
                if (MODE == 0) {
                    const int hh   = col / 192;
                    const int rem  = col - hh*192;
                    const int whch = rem >> 6;
                    const int d    = rem & 63;
                    const int ss   = rowg >> 1, bb = rowg & 1;
                    const size_t dst = ((size_t)(bb*16 + hh) * S_ + ss) * HD_ + d;
                    if (whch == 0) { v0 *= 0.18033688011f; v1 *= 0.18033688011f; }  // log2(e)/8
                    __half* dp = (whch == 0) ? qq : (whch == 1) ? kk : vv;
                    *(__half2*)&dp[dst] = __floats2half2_rn(v0, v1);
                } else if (MODE == 1) {
                    const size_t off = (size_t)rowg * N + col;
                    *(__half2*)&C16[off] = __floats2half2_rn(gelu_tanh(v0), gelu_tanh(v1));
                } else {
                    const size_t off = (size_t)rowg * N + col;
                    float2 rr = *(const float2*)&resid[off];
                    float2 o; o.x = v0 + rr.x; o.y = v1 + rr.y;
                    *(float2*)&C[off] = o;
                }
            }
        }
    }
}

// ---------------- Flash attention (fp16 HMMA, causal) ----------------
// BQ=128, KV staged 128 rows/buffer (computed as two 64-row halves), 8 warps,
// 2 CTAs/SM. 1-term QK^T / PV, exp2 softmax. Single-sync pipeline; dual-path
// (branch-free vs sub-tile-skip) inner loops.
// smem: Q(16K) + 2 x [K(16K) V(16K)] = 80KB dynamic.
static constexpr int FLASH_SMEM = 80*1024 + 1024;

__global__ void __launch_bounds__(256, 2)
flash_mma(const __half* __restrict__ Q, const __half* __restrict__ K,
          const __half* __restrict__ V, __half* __restrict__ Out)
{
    extern __shared__ char smem[];
    const uint32_t sq  = (smem_u32(smem) + 1023) & ~1023u;
    const uint32_t skv = sq + 16384;   // + buf*32768; within: K 0, V 16384

    const int tid  = threadIdx.x;
    const int lane = tid & 31;
    const int wq   = tid >> 5;
    const int bhid = blockIdx.y;
    const int bb   = bhid >> 4;
    const int hh   = bhid & 15;
    const int qi   = (int)gridDim.x - 1 - (int)blockIdx.x;   // heavy tiles first
    const int q0   = qi << 7;
    const int nt128 = (q0 >> 7) + 1;   // 128-wide KV tiles (last = diagonal)

    const size_t hbase = (size_t)bhid * (S_ * HD_);

    // ---- prologue: Q + KV tile 0 ----
    #pragma unroll
    for (int i = 0; i < 4; i++) {
        const int idx = tid*4 + i;
        const int row = idx >> 3, cc = idx & 7;
        const uint32_t off = row*128 + (uint32_t)((cc ^ (row & 7)) << 4);
        const size_t src = hbase + (size_t)(q0 + row) * HD_ + cc*8;
        cp16(sq + off, Q + src);
    }
    #pragma unroll
    for (int i = 0; i < 4; i++) {
        const int idx = tid*4 + i;          // 0..1023: 128 rows x 8 chunks
        const int row = idx >> 3, cc = idx & 7;
        const uint32_t off = row*128 + (uint32_t)((cc ^ (row & 7)) << 4);
        const size_t src = hbase + (size_t)row * HD_ + cc*8;
        cp16(skv + off,         K + src);
        cp16(skv + 16384 + off, V + src);
    }
    CP_COMMIT();
    CP_WAIT(0);
    __syncthreads();

    // ---- Q fragments (registers) ----
    uint32_t qf[4][4];
    {
        const int row = wq*16 + (lane & 15);
        #pragma unroll
        for (int ks = 0; ks < 4; ks++) {
            const int cc = 2*ks + (lane >> 4);
            const uint32_t off = row*128 + (uint32_t)((cc ^ (row & 7)) << 4);
            ldsm4(qf[ks], sq + off);
        }
    }

    float m_i[2] = {-1e30f, -1e30f};
    float l_i[2] = {0.f, 0.f};
    float O[8][4];
    #pragma unroll
    for (int j = 0; j < 8; j++)
        #pragma unroll
        for (int q = 0; q < 4; q++) O[j][q] = 0.f;

    const int my_last_row = q0 + wq*16 + 15;
    const int krow_b = (lane & 7) + ((lane >> 4) << 3);
    const int vrow_b = (lane & 7) + (((lane >> 3) & 1) << 3);

    for (int kt = 0; kt < nt128; kt++) {
        if (kt > 0) {
            CP_WAIT(0);        // kv(kt) landed
            __syncthreads();   // all warps done with buf[(kt+1)&1]'s old contents
        }
        if (kt + 1 < nt128) {
            const uint32_t stg = skv + ((kt+1) & 1) * 32768;
            const int tn0 = (kt+1) << 7;
            #pragma unroll
            for (int i = 0; i < 4; i++) {
                const int idx = tid*4 + i;
                const int row = idx >> 3, cc = idx & 7;
                const uint32_t off = row*128 + (uint32_t)((cc ^ (row & 7)) << 4);
                const size_t src = hbase + (size_t)(tn0 + row) * HD_ + cc*8;
                cp16(stg + off,         K + src);
                cp16(stg + 16384 + off, V + src);
            }
            CP_COMMIT();
        }

        const uint32_t buf = skv + (kt & 1) * 32768;
        const bool diag = (kt == nt128 - 1);

        #pragma unroll
        for (int hf = 0; hf < 2; hf++) {
            const int t0 = (kt << 7) + hf*64;
            if (t0 > my_last_row) continue;   // half fully masked for this warp

            const uint32_t sk = buf + hf*8192;
            const uint32_t sv = buf + 16384 + hf*8192;
            const bool full = (t0 + 48 <= my_last_row);

            // ---- scores S = Q K^T ----
            float sc[8][4];
            #pragma unroll
            for (int j = 0; j < 8; j++)
                #pragma unroll
                for (int q = 0; q < 4; q++) sc[j][q] = 0.f;

            if (full) {
                #pragma unroll
                for (int ks = 0; ks < 4; ks++) {
                    const int cc = 2*ks + ((lane >> 3) & 1);
                    #pragma unroll
                    for (int jt = 0; jt < 4; jt++) {
                        uint32_t bf[4];
                        const int row = jt*16 + krow_b;
                        const uint32_t off = row*128 + (uint32_t)((cc ^ (row & 7)) << 4);
                        ldsm4(bf, sk + off);
                        mma16816h(sc[2*jt],   qf[ks], &bf[0]);
                        mma16816h(sc[2*jt+1], qf[ks], &bf[2]);
                    }
                }
            } else {
                for (int jt = 0; jt < 4; jt++) {
                    if (t0 + jt*16 > my_last_row) break;
                    const int row = jt*16 + krow_b;
                    #pragma unroll
                    for (int ks = 0; ks < 4; ks++) {
                        uint32_t bf[4];
                        const int cc = 2*ks + ((lane >> 3) & 1);
                        const uint32_t off = row*128 + (uint32_t)((cc ^ (row & 7)) << 4);
                        ldsm4(bf, sk + off);
                        mma16816h(sc[2*jt],   qf[ks], &bf[0]);
                        mma16816h(sc[2*jt+1], qf[ks], &bf[2]);
                    }
                }
            }

            // ---- causal mask (diagonal 128-tile only) ----
            if (diag) {
                const int r0g = q0 + wq*16 + (lane >> 2);
                #pragma unroll
                for (int j = 0; j < 8; j++) {
                    const int c0 = t0 + j*8 + (lane & 3)*2;
                    if (c0     > r0g)     sc[j][0] = -1e30f;
                    if (c0 + 1 > r0g)     sc[j][1] = -1e30f;
                    if (c0     > r0g + 8) sc[j][2] = -1e30f;
                    if (c0 + 1 > r0g + 8) sc[j][3] = -1e30f;
                }
            }

            // ---- online softmax in log2 domain ----
            #pragma unroll
            for (int v = 0; v < 2; v++) {
                float rm = -1e30f;
                #pragma unroll
                for (int j = 0; j < 8; j++)
                    rm = fmaxf(rm, fmaxf(sc[j][2*v], sc[j][2*v+1]));
                rm = fmaxf(rm, __shfl_xor_sync(0xffffffffu, rm, 1));
                rm = fmaxf(rm, __shfl_xor_sync(0xffffffffu, rm, 2));
                const float mnew = fmaxf(m_i[v], rm);
                const float corr = exp2f(m_i[v] - mnew);
                float rs = 0.f;
                #pragma unroll
                for (int j = 0; j < 8; j++) {
                    float p0 = exp2f(sc[j][2*v]   - mnew);
                    float p1 = exp2f(sc[j][2*v+1] - mnew);
                    sc[j][2*v] = p0; sc[j][2*v+1] = p1;
                    rs += p0 + p1;
                }
                rs += __shfl_xor_sync(0xffffffffu, rs, 1);
                rs += __shfl_xor_sync(0xffffffffu, rs, 2);
                l_i[v] = l_i[v] * corr + rs;
                m_i[v] = mnew;
                #pragma unroll
                for (int j = 0; j < 8; j++) { O[j][2*v] *= corr; O[j][2*v+1] *= corr; }
            }

            // ---- O += P V ----
            if (full) {
                #pragma unroll
                for (int kc = 0; kc < 4; kc++) {
                    uint32_t pah[4];
                    {
                        __half2 h2;
                        h2 = __floats2half2_rn(sc[2*kc][0],   sc[2*kc][1]);   pah[0] = *(uint32_t*)&h2;
                        h2 = __floats2half2_rn(sc[2*kc][2],   sc[2*kc][3]);   pah[1] = *(uint32_t*)&h2;
                        h2 = __floats2half2_rn(sc[2*kc+1][0], sc[2*kc+1][1]); pah[2] = *(uint32_t*)&h2;
                        h2 = __floats2half2_rn(sc[2*kc+1][2], sc[2*kc+1][3]); pah[3] = *(uint32_t*)&h2;
                    }
                    const int vrow = kc*16 + vrow_b;
                    #pragma unroll
                    for (int p = 0; p < 4; p++) {
                        const int cc = 2*p + (lane >> 4);
                        const uint32_t off = vrow*128 + (uint32_t)((cc ^ (vrow & 7)) << 4);
                        uint32_t vf[4];
                        ldsm4t(vf, sv + off);
                        mma16816h(O[2*p],   pah, &vf[0]);
                        mma16816h(O[2*p+1], pah, &vf[2]);
                    }
                }
            } else {
                for (int kc = 0; kc < 4; kc++) {
                    if (t0 + kc*16 > my_last_row) break;   // P cols there are 0
                    uint32_t pah[4];
                    {
                        __half2 h2;
                        h2 = __floats2half2_rn(sc[2*kc][0],   sc[2*kc][1]);   pah[0] = *(uint32_t*)&h2;
                        h2 = __floats2half2_rn(sc[2*kc][2],   sc[2*kc][3]);   pah[1] = *(uint32_t*)&h2;
                        h2 = __floats2half2_rn(sc[2*kc+1][0], sc[2*kc+1][1]); pah[2] = *(uint32_t*)&h2;
                        h2 = __floats2half2_rn(sc[2*kc+1][2], sc[2*kc+1][3]); pah[3] = *(uint32_t*)&h2;
                    }
                    const int vrow = kc*16 + vrow_b;
                    #pragma unroll
                    for (int p = 0; p < 4; p++) {
                        const int cc = 2*p + (lane >> 4);
                        const uint32_t off = vrow*128 + (uint32_t)((cc ^ (vrow & 7)) << 4);
                        uint32_t vf[4];
                        ldsm4t(vf, sv + off);
                        mma16816h(O[2*p],   pah, &vf[0]);
                        mma16816h(O[2*p+1], pah, &vf[2]);
                    }
                }
            }
        }
    }

    // ---- epilogue: normalize + store fp16 ----
    #pragma unroll
    for (int v = 0; v < 2; v++) {
        const float inv = 1.f / l_i[v];
        const int srow = q0 + wq*16 + (lane >> 2) + v*8;
        const size_t base = ((size_t)srow * B_ + bb) * H_ + hh*HD_ + (lane & 3)*2;
        #pragma unroll
        for (int j = 0; j < 8; j++) {
            __half2 h2 = __floats2half2_rn(O[j][2*v] * inv, O[j][2*v+1] * inv);
            *(__half2*)&Out[base + j*8] = h2;
        }
    }
}

// ---------------- host ----------------
typedef CUresult (CUDAAPI *TMEncodeFn)(
    CUtensorMap*, CUtensorMapDataType, cuuint32_t, void*,
    const cuuint64_t*, const cuuint64_t*, const cuuint32_t*, const cuuint32_t*,
    CUtensorMapInterleave, CUtensorMapSwizzle, CUtensorMapL2promotion, CUtensorMapFloatOOBfill);

static void enc_map(TMEncodeFn fn, CUtensorMap* m, void* p, uint64_t rows, uint64_t k)
{
    cuuint64_t dims[2]    = {k, rows};
    cuuint64_t strides[1] = {k * 2};
    cuuint32_t box[2]     = {64, 128};
    cuuint32_t es[2]      = {1, 1};
    fn(m, CU_TENSOR_MAP_DATA_TYPE_FLOAT16, 2, p, dims, strides, box, es,
       CU_TENSOR_MAP_INTERLEAVE_NONE, CU_TENSOR_MAP_SWIZZLE_128B,
       CU_TENSOR_MAP_L2_PROMOTION_L2_128B, CU_TENSOR_MAP_FLOAT_OOB_FILL_NONE);
}

extern "C" void kernel_launch(void* const* d_in, const int* in_sizes, int n_in,
                              void* d_out, int out_size)
{
    const float* x     = (const float*)d_in[0];
    const float* ln1w  = (const float*)d_in[1];
    const float* ln1b  = (const float*)d_in[2];
    const float* wqkv  = (const float*)d_in[3];
    const float* bqkv  = (const float*)d_in[4];
    const float* wproj = (const float*)d_in[5];
    const float* bproj = (const float*)d_in[6];
    const float* ln2w  = (const float*)d_in[7];
    const float* ln2b  = (const float*)d_in[8];
    const float* wfc1  = (const float*)d_in[9];
    const float* bfc1  = (const float*)d_in[10];
    const float* wfc2  = (const float*)d_in[11];
    const float* bfc2  = (const float*)d_in[12];
    float* out = (float*)d_out;

    float *x1;
    __half *a16, *m16, *wq16, *wp16, *w116, *w216, *qq, *kk, *vv;
    cudaGetSymbolAddress((void**)&x1,   g_x1);
    cudaGetSymbolAddress((void**)&a16,  g_a);
    cudaGetSymbolAddress((void**)&m16,  g_m);
    cudaGetSymbolAddress((void**)&wq16, g_wqkv);
    cudaGetSymbolAddress((void**)&wp16, g_wproj);
    cudaGetSymbolAddress((void**)&w116, g_wfc1);
    cudaGetSymbolAddress((void**)&w216, g_wfc2);
    cudaGetSymbolAddress((void**)&qq,   g_q);
    cudaGetSymbolAddress((void**)&kk,   g_k);
    cudaGetSymbolAddress((void**)&vv,   g_v);

    TMEncodeFn enc = nullptr;
    cudaDriverEntryPointQueryResult qres;
    cudaGetDriverEntryPointByVersion("cuTensorMapEncodeTiled", (void**)&enc, 12000,
                                     cudaEnableDefault, &qres);

    cudaFuncSetAttribute((const void*)gemm_tc<0>, cudaFuncAttributeMaxDynamicSharedMemorySize, SMEM_BYTES);
    cudaFuncSetAttribute((const void*)gemm_tc<1>, cudaFuncAttributeMaxDynamicSharedMemorySize, SMEM_BYTES);
    cudaFuncSetAttribute((const void*)gemm_tc<2>, cudaFuncAttributeMaxDynamicSharedMemorySize, SMEM_BYTES);
    cudaFuncSetAttribute((const void*)flash_mma,  cudaFuncAttributeMaxDynamicSharedMemorySize, FLASH_SMEM);

    CUtensorMap mA, mB;

    // 0+1) fused: convert all weights fp16 + ln1 -> a16
    fused_prep<<<ROWS + (N4_ALL + 255)/256, 256>>>(x, ln1w, ln1b, a16,
        wqkv, wproj, wfc1, wfc2, wq16, wp16, w116, w216);
    // 2) qkv GEMM -> scatter Q/K/V : [4096,3072], K=1024
    enc_map(enc, &mA, a16, ROWS, H_);
    enc_map(enc, &mB, wq16, H3, H_);
    gemm_tc<0><<<dim3(H3/128, ROWS/128), 288, SMEM_BYTES>>>(
        mA, mB, bqkv, nullptr, nullptr, nullptr, qq, kk, vv, H3, H_/64);
    // 3) flash attention -> a16
    flash_mma<<<dim3(S_/128, BHN), 256, FLASH_SMEM>>>(qq, kk, vv, a16);
    // 4) x1 = x + attn @ wproj^T + b : [4096,1024], K=1024
    enc_map(enc, &mB, wp16, H_, H_);
    gemm_tc<2><<<dim3(H_/128, ROWS/128), 288, SMEM_BYTES>>>(
        mA, mB, bproj, x, x1, nullptr, nullptr, nullptr, nullptr, H_, H_/64);
    // 5) ln2 -> a16
    ln_h<<<ROWS, 256>>>(x1, ln2w, ln2b, a16);
    // 6) mid = gelu(ln2 @ wfc1^T + b) -> m16 : [4096,4096], K=1024
    enc_map(enc, &mB, w116, H4, H_);
    gemm_tc<1><<<dim3(H4/128, ROWS/128), 288, SMEM_BYTES>>>(
        mA, mB, bfc1, nullptr, nullptr, m16, nullptr, nullptr, nullptr, H4, H_/64);
    // 7) out = x1 + mid @ wfc2^T + b : [4096,1024], K=4096
    enc_map(enc, &mA, m16, ROWS, H4);
    enc_map(enc, &mB, w216, H_, H4);
    gemm_tc<2><<<dim3(H_/128, ROWS/128), 288, SMEM_BYTES>>>(
        mA, mB, bfc2, x1, out, nullptr, nullptr, nullptr, nullptr, H_, H4/64);
}

// round 14
// speedup vs baseline: 1.0136x; 1.0136x over previous
#include <cuda_runtime.h>
#include <cuda.h>
#include <cuda_fp16.h>
#include <math.h>
#include <stdint.h>

// Problem dims (fixed by reference)
#define S_    2048
#define B_    2
#define H_    1024
#define NH_   16
#define HD_   64
#define ROWS  (S_*B_)      // 4096
#define H3    (3*H_)       // 3072
#define H4    (4*H_)       // 4096
#define BHN   (B_*NH_)     // 32

// ---------------- scratch (no allocations allowed) ----------------
__device__ float   g_x1   [ROWS*(size_t)H_];   // fp32 post-attn residual
__device__ __half  g_a    [ROWS*(size_t)H_];   // activation (single fp16)
__device__ __half  g_m    [ROWS*(size_t)H4];   // mid (fc2 input)
__device__ __half  g_wqkv [H3*(size_t)H_];
__device__ __half  g_wproj[H_*(size_t)H_];
__device__ __half  g_wfc1 [H4*(size_t)H_];
__device__ __half  g_wfc2 [H_*(size_t)H4];
// Q,K,V single fp16, layout [(b*16+h), s, d]
__device__ __half  g_q [BHN*(size_t)S_*HD_];
__device__ __half  g_k [BHN*(size_t)S_*HD_];
__device__ __half  g_v [BHN*(size_t)S_*HD_];

// ---------------- PTX helpers ----------------
__device__ __forceinline__ uint32_t smem_u32(const void* p) {
    uint32_t a;
    asm("{ .reg .u64 t; cvta.to.shared.u64 t, %1; cvt.u32.u64 %0, t; }" : "=r"(a) : "l"(p));
    return a;
}

// guaranteed single-MUFU exp2 (independent of -use_fast_math)
__device__ __forceinline__ float ex2(float x) {
    float r;
    asm("ex2.approx.f32 %0, %1;" : "=f"(r) : "f"(x));
    return r;
}

#define MBARRIER_INIT(addr, cnt) \
    asm volatile("mbarrier.init.shared.b64 [%0], %1;" :: "r"(addr), "r"(cnt) : "memory")
#define MBARRIER_ARRIVE(addr) \
    asm volatile("mbarrier.arrive.shared.b64 _, [%0];" :: "r"(addr) : "memory")
#define MBARRIER_EXPECT_TX(addr, bytes) \
    asm volatile("mbarrier.arrive.expect_tx.shared.b64 _, [%0], %1;" :: "r"(addr), "r"(bytes) : "memory")

#define MBARRIER_WAIT_PARITY(addr, phase) do { \
    uint32_t _m = (addr); uint32_t _p = (phase); uint32_t _d; \
    asm volatile("{\n\t.reg .pred p;\n\t" \
        "mbarrier.try_wait.parity.acquire.cta.shared::cta.b64 p, [%1], %2;\n\t" \
        "selp.b32 %0, 1, 0, p;\n\t}" : "=r"(_d) : "r"(_m), "r"(_p) : "memory"); \
    if (!_d) { \
        asm volatile("{\n\t.reg .pred P1;\n\t" \
            "WL_%=:\n\t" \
            "mbarrier.try_wait.parity.acquire.cta.shared::cta.b64 P1, [%0], %1, 0x989680;\n\t" \
            "@P1 bra.uni WD_%=;\n\t" \
            "bra.uni WL_%=;\n\t" \
            "WD_%=:\n\t}" :: "r"(_m), "r"(_p) : "memory"); \
    } \
} while (0)

#define MBARRIER_WAIT_PARITY_RELAXED(addr, phase) do { \
    uint32_t _m = (addr); uint32_t _p = (phase); uint32_t _d; \
    asm volatile("{\n\t.reg .pred p;\n\t" \
        "mbarrier.try_wait.parity.relaxed.cta.shared::cta.b64 p, [%1], %2, 0x989680;\n\t" \
        "selp.b32 %0, 1, 0, p;\n\t}" : "=r"(_d) : "r"(_m), "r"(_p) : "memory"); \
    if (!_d) { \
        asm volatile("{\n\t.reg .pred P1;\n\t" \
            "WL_%=:\n\t" \
            "mbarrier.try_wait.parity.relaxed.cta.shared::cta.b64 P1, [%0], %1, 0x989680;\n\t" \
            "@P1 bra.uni WD_%=;\n\t" \
            "bra.uni WL_%=;\n\t" \
            "WD_%=:\n\t}" :: "r"(_m), "r"(_p) : "memory"); \
    } \
} while (0)

__device__ __forceinline__ void tma2d(uint32_t dst, const void* map, int x, int y, uint32_t mbar) {
    asm volatile("cp.async.bulk.tensor.2d.shared::cta.global.tile.mbarrier::complete_tx::bytes "
                 "[%0], [%1, {%2, %3}], [%4];"
                 :: "r"(dst), "l"(map), "r"(x), "r"(y), "r"(mbar) : "memory");
}

__device__ __forceinline__ void ldsm4(uint32_t* r, uint32_t addr) {
    asm volatile("ldmatrix.sync.aligned.m8n8.x4.shared.b16 {%0,%1,%2,%3}, [%4];"
                 : "=r"(r[0]), "=r"(r[1]), "=r"(r[2]), "=r"(r[3]) : "r"(addr));
}
__device__ __forceinline__ void ldsm4t(uint32_t* r, uint32_t addr) {
    asm volatile("ldmatrix.sync.aligned.m8n8.x4.trans.shared.b16 {%0,%1,%2,%3}, [%4];"
                 : "=r"(r[0]), "=r"(r[1]), "=r"(r[2]), "=r"(r[3]) : "r"(addr));
}

__device__ __forceinline__ void mma16816h(float* d, const uint32_t* a, const uint32_t* b) {
    asm volatile("mma.sync.aligned.m16n8k16.row.col.f32.f16.f16.f32 "
                 "{%0,%1,%2,%3}, {%4,%5,%6,%7}, {%8,%9}, {%0,%1,%2,%3};"
                 : "+f"(d[0]), "+f"(d[1]), "+f"(d[2]), "+f"(d[3])
                 : "r"(a[0]), "r"(a[1]), "r"(a[2]), "r"(a[3]), "r"(b[0]), "r"(b[1]));
}

__device__ __forceinline__ void cp16(uint32_t dst, const void* src) {
    asm volatile("cp.async.cg.shared.global [%0], [%1], 16;" :: "r"(dst), "l"(src) : "memory");
}
#define CP_COMMIT() asm volatile("cp.async.commit_group;" ::: "memory")
#define CP_WAIT(n)  asm volatile("cp.async.wait_group %0;" :: "n"(n) : "memory")

__device__ __forceinline__ float gelu_tanh(float u) {
    float c = 0.7978845608028654f * (u + 0.044715f * u * u * u);
    return 0.5f * u * (1.f + tanhf(c));
}

// ---------------- LayerNorm row body (fp16 out) ----------------
__device__ __forceinline__ void ln_row(const float* __restrict__ x, const float* __restrict__ w,
                                       const float* __restrict__ b, __half* __restrict__ y, int row)
{
    const int t = threadIdx.x;
    float4 v = ((const float4*)(x + (size_t)row * H_))[t];
    float s  = v.x + v.y + v.z + v.w;
    float sq = v.x*v.x + v.y*v.y + v.z*v.z + v.w*v.w;
    #pragma unroll
    for (int o = 16; o > 0; o >>= 1) {
        s  += __shfl_xor_sync(0xffffffffu, s,  o);
        sq += __shfl_xor_sync(0xffffffffu, sq, o);
    }
    __shared__ float ss[8], ssq[8];
    const int wid = t >> 5, lid = t & 31;
    if (lid == 0) { ss[wid] = s; ssq[wid] = sq; }
    __syncthreads();
    if (wid == 0) {
        float s2 = (lid < 8) ? ss[lid]  : 0.f;
        float q2 = (lid < 8) ? ssq[lid] : 0.f;
        #pragma unroll
        for (int o = 4; o > 0; o >>= 1) {
            s2 += __shfl_xor_sync(0xffffffffu, s2, o);
            q2 += __shfl_xor_sync(0xffffffffu, q2, o);
        }
        if (lid == 0) { ss[0] = s2; ssq[0] = q2; }
    }
    __syncthreads();
    const float mean = ss[0] * (1.f / H_);
    const float var  = ssq[0] * (1.f / H_) - mean * mean;
    const float rstd = rsqrtf(var + 1e-5f);
    float4 wv = ((const float4*)w)[t];
    float4 bv = ((const float4*)b)[t];
    float y0 = (v.x - mean) * rstd * wv.x + bv.x;
    float y1 = (v.y - mean) * rstd * wv.y + bv.y;
    float y2 = (v.z - mean) * rstd * wv.z + bv.z;
    float y3 = (v.w - mean) * rstd * wv.w + bv.w;
    __half2* yp = (__half2*)(y + (size_t)row * H_);
    yp[t*2]   = __floats2half2_rn(y0, y1);
    yp[t*2+1] = __floats2half2_rn(y2, y3);
}

__global__ void __launch_bounds__(256)
ln_h(const float* __restrict__ x, const float* __restrict__ w, const float* __restrict__ b,
     __half* __restrict__ y)
{
    ln_row(x, w, b, y, blockIdx.x);
}

// ---------------- fused: ln1 + all-weight fp32->fp16 convert ----------------
#define N4_QKV  (H3*H_/4)
#define N4_PROJ (H_*H_/4)
#define N4_FC1  (H4*H_/4)
#define N4_FC2  (H_*H4/4)
#define N4_ALL  (N4_QKV + N4_PROJ + N4_FC1 + N4_FC2)

__global__ void __launch_bounds__(256)
fused_prep(const float* __restrict__ x, const float* __restrict__ ln1w, const float* __restrict__ ln1b,
           __half* __restrict__ a16,
           const float* __restrict__ w0, const float* __restrict__ w1,
           const float* __restrict__ w2, const float* __restrict__ w3,
           __half* __restrict__ o0, __half* __restrict__ o1,
           __half* __restrict__ o2, __half* __restrict__ o3)
{
    if (blockIdx.x < ROWS) { ln_row(x, ln1w, ln1b, a16, blockIdx.x); return; }
    int i = (blockIdx.x - ROWS) * 256 + threadIdx.x;
    if (i >= N4_ALL) return;
    const float* s; __half* d; int k = i;
    if (k < N4_QKV)                    { s = w0; d = o0; }
    else if ((k -= N4_QKV)  < N4_PROJ) { s = w1; d = o1; }
    else if ((k -= N4_PROJ) < N4_FC1)  { s = w2; d = o2; }
    else { k -= N4_FC1;                  s = w3; d = o3; }
    float4 v = ((const float4*)s)[k];
    ((__half2*)d)[2*k]   = __floats2half2_rn(v.x, v.y);
    ((__half2*)d)[2*k+1] = __floats2half2_rn(v.z, v.w);
}

// ---------------- fp16 1-term GEMM (non-persistent, frozen) ----------------
// MODE 0: +bias -> scatter Q (scaled log2e/8), K, V (single fp16)
// MODE 1: gelu(+bias) -> fp16 C16
// MODE 2: +bias+resid -> fp32 C
static constexpr int SMEM_BYTES = 3*32768 + 1024;

template<int MODE>
__global__ void __launch_bounds__(288, 2)
gemm_tc(const __grid_constant__ CUtensorMap mA,
        const __grid_constant__ CUtensorMap mB,
        const float* __restrict__ bias, const float* __restrict__ resid,
        float* __restrict__ C, __half* __restrict__ C16,
        __half* __restrict__ qq, __half* __restrict__ kk, __half* __restrict__ vv,
        int N, int nc)
{
    extern __shared__ char smem[];
    const uint32_t sb  = smem_u32(smem);
    const uint32_t st0 = (sb + 64 + 1023) & ~1023u;
    const int tid = threadIdx.x;

    if (tid == 0) {
        #pragma unroll
        for (int i = 0; i < 3; i++) {
            MBARRIER_INIT(sb + 8*i, 1);
            MBARRIER_INIT(sb + 24 + 8*i, 8);
        }
    }
    __syncthreads();

    const int bx = blockIdx.x, by = blockIdx.y;

    if (tid >= 256) {
        if (tid == 256) {
            for (int c = 0; c < nc; c++) {
                const int s = c % 3, r = c / 3;
                const uint32_t stg = st0 + s * 32768;
                if (r > 0) MBARRIER_WAIT_PARITY_RELAXED(sb + 24 + 8*s, (r - 1) & 1);
                MBARRIER_EXPECT_TX(sb + 8*s, 32768u);
                const int kx = c * 64;
                tma2d(stg,         &mA, kx, by * 128, sb + 8*s);
                tma2d(stg + 16384, &mB, kx, bx * 128, sb + 8*s);
            }
        }
        return;
    }

    const int lane = tid & 31;
    const int wm = (tid >> 5) >> 1;
    const int wn = (tid >> 5) & 1;

    const int arow0 = wm*32 + (lane & 15);
    const int acx   = lane >> 4;
    const int brow0 = wn*64 + (lane & 7) + ((lane >> 4) << 3);
    const int bcx   = (lane >> 3) & 1;

    float acc[2][8][4];
    #pragma unroll
    for (int i = 0; i < 2; i++)
        #pragma unroll
        for (int j = 0; j < 8; j++)
            #pragma unroll
            for (int q = 0; q < 4; q++) acc[i][j][q] = 0.f;

    for (int c = 0; c < nc; c++) {
        const int s = c % 3, r = c / 3;
        const uint32_t stg = st0 + s * 32768;
        MBARRIER_WAIT_PARITY(sb + 8*s, r & 1);

        #pragma unroll
        for (int ks = 0; ks < 4; ks++) {
            uint32_t af[2][4], bf[4][4];
            #pragma unroll
            for (int i = 0; i < 2; i++) {
                const int row = arow0 + i*16;
                const int cc  = 2*ks + acx;
                const uint32_t off = row*128 + (((uint32_t)(cc ^ (row & 7))) << 4);
                ldsm4(af[i], stg + off);
            }
            #pragma unroll
            for (int jt = 0; jt < 4; jt++) {
                const int row = brow0 + jt*16;
                const int cc  = 2*ks + bcx;
                const uint32_t off = row*128 + (((uint32_t)(cc ^ (row & 7))) << 4);
                ldsm4(bf[jt], stg + 16384 + off);
            }
            #pragma unroll
            for (int i = 0; i < 2; i++)
                #pragma unroll
                for (int j = 0; j < 8; j++)
                    mma16816h(acc[i][j], af[i], &bf[j>>1][(j&1)*2]);
        }
        if (lane == 0) MBARRIER_ARRIVE(sb + 24 + 8*s);
    }

    // ---- epilogue ----
    const int rbase = by*128 + wm*32 + (lane >> 2);
    const int cbase = bx*128 + wn*64 + (lane & 3)*2;
    #pragma unroll
    for (int j = 0; j < 8; j++) {
        const int col = cbase + j*8;
        const float bx0 = bias[col], bx1 = bias[col + 1];
        #pragma unroll
        for (int i = 0; i < 2; i++) {
            #pragma unroll
            for (int half = 0; half < 2; half++) {
                const int rowg = rbase + i*16 + half*8;
                float v0 = acc[i][j][half*2 + 0] + bx0;
                float v1 = acc[i][j][half*2 + 1] + bx1;
                if (MODE == 0) {
                    const int hh   = col / 192;
                    const int rem  = col - hh*192;
                    const int whch = rem >> 6;
                    const int d    = rem & 63;
                    const int ss   = rowg >> 1, bb = rowg & 1;
                    const size_t dst = ((size_t)(bb*16 + hh) * S_ + ss) * HD_ + d;
                    if (whch == 0) { v0 *= 0.18033688011f; v1 *= 0.18033688011f; }  // log2(e)/8
                    __half* dp = (whch == 0) ? qq : (whch == 1) ? kk : vv;
                    *(__half2*)&dp[dst] = __floats2half2_rn(v0, v1);
                } else if (MODE == 1) {
                    const size_t off = (size_t)rowg * N + col;
                    *(__half2*)&C16[off] = __floats2half2_rn(gelu_tanh(v0), gelu_tanh(v1));
                } else {
                    const size_t off = (size_t)rowg * N + col;
                    float2 rr = *(const float2*)&resid[off];
                    float2 o; o.x = v0 + rr.x; o.y = v1 + rr.y;
                    *(float2*)&C[off] = o;
                }
            }
        }
    }
}

// ---------------- Flash attention (fp16 HMMA, causal) ----------------
// BQ=128, BKV=64, 8 warps, 2 CTAs/SM. 1-term QK^T / PV, ex2.approx softmax.
// Single-sync pipeline; dual-path (branch-free vs sub-tile-skip) inner loops.
static constexpr int FLASH_SMEM = 48*1024 + 1024;

__global__ void __launch_bounds__(256, 2)
flash_mma(const __half* __restrict__ Q, const __half* __restrict__ K,
          const __half* __restrict__ V, __half* __restrict__ Out)
{
    extern __shared__ char smem[];
    const uint32_t sq  = (smem_u32(smem) + 1023) & ~1023u;
    const uint32_t skv = sq + 16384;   // + buf*16384; within: K 0, V 8192

    const int tid  = threadIdx.x;
    const int lane = tid & 31;
    const int wq   = tid >> 5;
    const int bhid = blockIdx.y;
    const int bb   = bhid >> 4;
    const int hh   = bhid & 15;
    const int qi   = (int)gridDim.x - 1 - (int)blockIdx.x;   // heavy tiles first
    const int q0   = qi << 7;
    const int ntiles = (q0 >> 6) + 2;

    const size_t hbase = (size_t)bhid * (S_ * HD_);

    // ---- prologue: Q + KV tile 0 ----
    #pragma unroll
    for (int i = 0; i < 4; i++) {
        const int idx = tid*4 + i;
        const int row = idx >> 3, cc = idx & 7;
        const uint32_t off = row*128 + (uint32_t)((cc ^ (row & 7)) << 4);
        const size_t src = hbase + (size_t)(q0 + row) * HD_ + cc*8;
        cp16(sq + off, Q + src);
    }
    #pragma unroll
    for (int i = 0; i < 2; i++) {
        const int idx = tid*2 + i;
        const int row = idx >> 3, cc = idx & 7;
        const uint32_t off = row*128 + (uint32_t)((cc ^ (row & 7)) << 4);
        const size_t src = hbase + (size_t)row * HD_ + cc*8;
        cp16(skv + off,        K + src);
        cp16(skv + 8192 + off, V + src);
    }
    CP_COMMIT();
    CP_WAIT(0);
    __syncthreads();

    // ---- Q fragments (registers) ----
    uint32_t qf[4][4];
    {
        const int row = wq*16 + (lane & 15);
        #pragma unroll
        for (int ks = 0; ks < 4; ks++) {
            const int cc = 2*ks + (lane >> 4);
            const uint32_t off = row*128 + (uint32_t)((cc ^ (row & 7)) << 4);
            ldsm4(qf[ks], sq + off);
        }
    }

    float m_i[2] = {-1e30f, -1e30f};
    float l_i[2] = {0.f, 0.f};
    float O[8][4];
    #pragma unroll
    for (int j = 0; j < 8; j++)
        #pragma unroll
        for (int q = 0; q < 4; q++) O[j][q] = 0.f;

    const int my_last_row = q0 + wq*16 + 15;

    for (int kt = 0; kt < ntiles; kt++) {
        const int t0 = kt << 6;
        if (kt > 0) {
            CP_WAIT(0);        // kv(kt) landed
            __syncthreads();   // all warps done with buf[(kt+1)&1]'s old contents
        }
        if (kt + 1 < ntiles) {
            const uint32_t stg = skv + ((kt+1) & 1) * 16384;
            const int tn0 = (kt+1) << 6;
            #pragma unroll
            for (int i = 0; i < 2; i++) {
                const int idx = tid*2 + i;
                const int row = idx >> 3, cc = idx & 7;
                const uint32_t off = row*128 + (uint32_t)((cc ^ (row & 7)) << 4);
                const size_t src = hbase + (size_t)(tn0 + row) * HD_ + cc*8;
                cp16(stg + off,        K + src);
                cp16(stg + 8192 + off, V + src);
            }
            CP_COMMIT();
        }

        if (t0 > my_last_row) continue;   // tile fully masked for this warp

        const uint32_t stg = skv + (kt & 1) * 16384;
        const uint32_t sk = stg, sv = stg + 8192;
        const bool full = (t0 + 48 <= my_last_row);   // all 4 sub-tiles live (warp-uniform)

        // ---- scores S = Q K^T ----
        float sc[8][4];
        #pragma unroll
        for (int j = 0; j < 8; j++)
            #pragma unroll
            for (int q = 0; q < 4; q++) sc[j][q] = 0.f;

        const int krow_b = (lane & 7) + ((lane >> 4) << 3);
        if (full) {
            #pragma unroll
            for (int ks = 0; ks < 4; ks++) {
                const int cc = 2*ks + ((lane >> 3) & 1);
                #pragma unroll
                for (int jt = 0; jt < 4; jt++) {
                    uint32_t bf[4];
                    const int row = jt*16 + krow_b;
                    const uint32_t off = row*128 + (uint32_t)((cc ^ (row & 7)) << 4);
                    ldsm4(bf, sk + off);
                    mma16816h(sc[2*jt],   qf[ks], &bf[0]);
                    mma16816h(sc[2*jt+1], qf[ks], &bf[2]);
                }
            }
        } else {
            for (int jt = 0; jt < 4; jt++) {
                if (t0 + jt*16 > my_last_row) break;
                const int row = jt*16 + krow_b;
                #pragma unroll
                for (int ks = 0; ks < 4; ks++) {
                    uint32_t bf[4];
                    const int cc = 2*ks + ((lane >> 3) & 1);
                    const uint32_t off = row*128 + (uint32_t)((cc ^ (row & 7)) << 4);
                    ldsm4(bf, sk + off);
                    mma16816h(sc[2*jt],   qf[ks], &bf[0]);
                    mma16816h(sc[2*jt+1], qf[ks], &bf[2]);
                }
            }
        }

        // ---- causal mask (last two kv tiles only) ----
        if (kt >= ntiles - 2) {
            const int r0g = q0 + wq*16 + (lane >> 2);
            #pragma unroll
            for (int j = 0; j < 8; j++) {
                const int c0 = t0 + j*8 + (lane & 3)*2;
                if (c0     > r0g)     sc[j][0] = -1e30f;
                if (c0 + 1 > r0g)     sc[j][1] = -1e30f;
                if (c0     > r0g + 8) sc[j][2] = -1e30f;
                if (c0 + 1 > r0g + 8) sc[j][3] = -1e30f;
            }
        }

        // ---- online softmax in log2 domain (single-MUFU ex2) ----
        #pragma unroll
        for (int v = 0; v < 2; v++) {
            float rm = -1e30f;
            #pragma unroll
            for (int j = 0; j < 8; j++)
                rm = fmaxf(rm, fmaxf(sc[j][2*v], sc[j][2*v+1]));
            rm = fmaxf(rm, __shfl_xor_sync(0xffffffffu, rm, 1));
            rm = fmaxf(rm, __shfl_xor_sync(0xffffffffu, rm, 2));
            const float mnew = fmaxf(m_i[v], rm);
            const float corr = ex2(m_i[v] - mnew);
            float rs = 0.f;
            #pragma unroll
            for (int j = 0; j < 8; j++) {
                float p0 = ex2(sc[j][2*v]   - mnew);
                float p1 = ex2(sc[j][2*v+1] - mnew);
                sc[j][2*v] = p0; sc[j][2*v+1] = p1;
                rs += p0 + p1;
            }
            rs += __shfl_xor_sync(0xffffffffu, rs, 1);
            rs += __shfl_xor_sync(0xffffffffu, rs, 2);
            l_i[v] = l_i[v] * corr + rs;
            m_i[v] = mnew;
            #pragma unroll
            for (int j = 0; j < 8; j++) { O[j][2*v] *= corr; O[j][2*v+1] *= corr; }
        }

        // ---- O += P V ----
        const int vrow_b = (lane & 7) + (((lane >> 3) & 1) << 3);
        if (full) {
            #pragma unroll
            for (int kc = 0; kc < 4; kc++) {
                uint32_t pah[4];
                {
                    __half2 h2;
                    h2 = __floats2half2_rn(sc[2*kc][0],   sc[2*kc][1]);   pah[0] = *(uint32_t*)&h2;
                    h2 = __floats2half2_rn(sc[2*kc][2],   sc[2*kc][3]);   pah[1] = *(uint32_t*)&h2;
                    h2 = __floats2half2_rn(sc[2*kc+1][0], sc[2*kc+1][1]); pah[2] = *(uint32_t*)&h2;
                    h2 = __floats2half2_rn(sc[2*kc+1][2], sc[2*kc+1][3]); pah[3] = *(uint32_t*)&h2;
                }
                const int vrow = kc*16 + vrow_b;
                #pragma unroll
                for (int p = 0; p < 4; p++) {
                    const int cc = 2*p + (lane >> 4);
                    const uint32_t off = vrow*128 + (uint32_t)((cc ^ (vrow & 7)) << 4);
                    uint32_t vf[4];
                    ldsm4t(vf, sv + off);
                    mma16816h(O[2*p],   pah, &vf[0]);
                    mma16816h(O[2*p+1], pah, &vf[2]);
                }
            }
        } else {
            for (int kc = 0; kc < 4; kc++) {
                if (t0 + kc*16 > my_last_row) break;   // P cols there are 0
                uint32_t pah[4];
                {
                    __half2 h2;
                    h2 = __floats2half2_rn(sc[2*kc][0],   sc[2*kc][1]);   pah[0] = *(uint32_t*)&h2;
                    h2 = __floats2half2_rn(sc[2*kc][2],   sc[2*kc][3]);   pah[1] = *(uint32_t*)&h2;
                    h2 = __floats2half2_rn(sc[2*kc+1][0], sc[2*kc+1][1]); pah[2] = *(uint32_t*)&h2;
                    h2 = __floats2half2_rn(sc[2*kc+1][2], sc[2*kc+1][3]); pah[3] = *(uint32_t*)&h2;
                }
                const int vrow = kc*16 + vrow_b;
                #pragma unroll
                for (int p = 0; p < 4; p++) {
                    const int cc = 2*p + (lane >> 4);
                    const uint32_t off = vrow*128 + (uint32_t)((cc ^ (vrow & 7)) << 4);
                    uint32_t vf[4];
                    ldsm4t(vf, sv + off);
                    mma16816h(O[2*p],   pah, &vf[0]);
                    mma16816h(O[2*p+1], pah, &vf[2]);
                }
            }
        }
    }

    // ---- epilogue: normalize + store fp16 ----
    #pragma unroll
    for (int v = 0; v < 2; v++) {
        const float inv = 1.f / l_i[v];
        const int srow = q0 + wq*16 + (lane >> 2) + v*8;
        const size_t base = ((size_t)srow * B_ + bb) * H_ + hh*HD_ + (lane & 3)*2;
        #pragma unroll
        for (int j = 0; j < 8; j++) {
            __half2 h2 = __floats2half2_rn(O[j][2*v] * inv, O[j][2*v+1] * inv);
            *(__half2*)&Out[base + j*8] = h2;
        }
    }
}

// ---------------- host ----------------
typedef CUresult (CUDAAPI *TMEncodeFn)(
    CUtensorMap*, CUtensorMapDataType, cuuint32_t, void*,
    const cuuint64_t*, const cuuint64_t*, const cuuint32_t*, const cuuint32_t*,
    CUtensorMapInterleave, CUtensorMapSwizzle, CUtensorMapL2promotion, CUtensorMapFloatOOBfill);

static void enc_map(TMEncodeFn fn, CUtensorMap* m, void* p, uint64_t rows, uint64_t k)
{
    cuuint64_t dims[2]    = {k, rows};
    cuuint64_t strides[1] = {k * 2};
    cuuint32_t box[2]     = {64, 128};
    cuuint32_t es[2]      = {1, 1};
    fn(m, CU_TENSOR_MAP_DATA_TYPE_FLOAT16, 2, p, dims, strides, box, es,
       CU_TENSOR_MAP_INTERLEAVE_NONE, CU_TENSOR_MAP_SWIZZLE_128B,
       CU_TENSOR_MAP_L2_PROMOTION_L2_128B, CU_TENSOR_MAP_FLOAT_OOB_FILL_NONE);
}

extern "C" void kernel_launch(void* const* d_in, const int* in_sizes, int n_in,
                              void* d_out, int out_size)
{
    const float* x     = (const float*)d_in[0];
    const float* ln1w  = (const float*)d_in[1];
    const float* ln1b  = (const float*)d_in[2];
    const float* wqkv  = (const float*)d_in[3];
    const float* bqkv  = (const float*)d_in[4];
    const float* wproj = (const float*)d_in[5];
    const float* bproj = (const float*)d_in[6];
    const float* ln2w  = (const float*)d_in[7];
    const float* ln2b  = (const float*)d_in[8];
    const float* wfc1  = (const float*)d_in[9];
    const float* bfc1  = (const float*)d_in[10];
    const float* wfc2  = (const float*)d_in[11];
    const float* bfc2  = (const float*)d_in[12];
    float* out = (float*)d_out;

    float *x1;
    __half *a16, *m16, *wq16, *wp16, *w116, *w216, *qq, *kk, *vv;
    cudaGetSymbolAddress((void**)&x1,   g_x1);
    cudaGetSymbolAddress((void**)&a16,  g_a);
    cudaGetSymbolAddress((void**)&m16,  g_m);
    cudaGetSymbolAddress((void**)&wq16, g_wqkv);
    cudaGetSymbolAddress((void**)&wp16, g_wproj);
    cudaGetSymbolAddress((void**)&w116, g_wfc1);
    cudaGetSymbolAddress((void**)&w216, g_wfc2);
    cudaGetSymbolAddress((void**)&qq,   g_q);
    cudaGetSymbolAddress((void**)&kk,   g_k);
    cudaGetSymbolAddress((void**)&vv,   g_v);

    TMEncodeFn enc = nullptr;
    cudaDriverEntryPointQueryResult qres;
    cudaGetDriverEntryPointByVersion("cuTensorMapEncodeTiled", (void**)&enc, 12000,
                                     cudaEnableDefault, &qres);

    cudaFuncSetAttribute((const void*)gemm_tc<0>, cudaFuncAttributeMaxDynamicSharedMemorySize, SMEM_BYTES);
    cudaFuncSetAttribute((const void*)gemm_tc<1>, cudaFuncAttributeMaxDynamicSharedMemorySize, SMEM_BYTES);
    cudaFuncSetAttribute((const void*)gemm_tc<2>, cudaFuncAttributeMaxDynamicSharedMemorySize, SMEM_BYTES);
    cudaFuncSetAttribute((const void*)flash_mma,  cudaFuncAttributeMaxDynamicSharedMemorySize, FLASH_SMEM);

    CUtensorMap mA, mB;

    // 0+1) fused: convert all weights fp16 + ln1 -> a16
    fused_prep<<<ROWS + (N4_ALL + 255)/256, 256>>>(x, ln1w, ln1b, a16,
        wqkv, wproj, wfc1, wfc2, wq16, wp16, w116, w216);
    // 2) qkv GEMM -> scatter Q/K/V : [4096,3072], K=1024
    enc_map(enc, &mA, a16, ROWS, H_);
    enc_map(enc, &mB, wq16, H3, H_);
    gemm_tc<0><<<dim3(H3/128, ROWS/128), 288, SMEM_BYTES>>>(
        mA, mB, bqkv, nullptr, nullptr, nullptr, qq, kk, vv, H3, H_/64);
    // 3) flash attention -> a16
    flash_mma<<<dim3(S_/128, BHN), 256, FLASH_SMEM>>>(qq, kk, vv, a16);
    // 4) x1 = x + attn @ wproj^T + b : [4096,1024], K=1024
    enc_map(enc, &mB, wp16, H_, H_);
    gemm_tc<2><<<dim3(H_/128, ROWS/128), 288, SMEM_BYTES>>>(
        mA, mB, bproj, x, x1, nullptr, nullptr, nullptr, nullptr, H_, H_/64);
    // 5) ln2 -> a16
    ln_h<<<ROWS, 256>>>(x1, ln2w, ln2b, a16);
    // 6) mid = gelu(ln2 @ wfc1^T + b) -> m16 : [4096,4096], K=1024
    enc_map(enc, &mB, w116, H4, H_);
    gemm_tc<1><<<dim3(H4/128, ROWS/128), 288, SMEM_BYTES>>>(
        mA, mB, bfc1, nullptr, nullptr, m16, nullptr, nullptr, nullptr, H4, H_/64);
    // 7) out = x1 + mid @ wfc2^T + b : [4096,1024], K=4096
    enc_map(enc, &mA, m16, ROWS, H4);
    enc_map(enc, &mB, w216, H_, H4);
    gemm_tc<2><<<dim3(H_/128, ROWS/128), 288, SMEM_BYTES>>>(
        mA, mB, bfc2, x1, out, nullptr, nullptr, nullptr, nullptr, H_, H4/64);
}

// round 15
// speedup vs baseline: 1.0262x; 1.0125x over previous
#include <cuda_runtime.h>
#include <cuda.h>
#include <cuda_fp16.h>
#include <math.h>
#include <stdint.h>

// Problem dims (fixed by reference)
#define S_    2048
#define B_    2
#define H_    1024
#define NH_   16
#define HD_   64
#define ROWS  (S_*B_)      // 4096
#define H3    (3*H_)       // 3072
#define H4    (4*H_)       // 4096
#define BHN   (B_*NH_)     // 32

// ---------------- scratch (no allocations allowed) ----------------
__device__ float   g_x1   [ROWS*(size_t)H_];   // fp32 post-attn residual
__device__ __half  g_a    [ROWS*(size_t)H_];   // activation (single fp16)
__device__ __half  g_m    [ROWS*(size_t)H4];   // mid (fc2 input)
__device__ __half  g_wqkv [H3*(size_t)H_];
__device__ __half  g_wproj[H_*(size_t)H_];
__device__ __half  g_wfc1 [H4*(size_t)H_];
__device__ __half  g_wfc2 [H_*(size_t)H4];
// Q,K,V single fp16, layout [(b*16+h), s, d]
__device__ __half  g_q [BHN*(size_t)S_*HD_];
__device__ __half  g_k [BHN*(size_t)S_*HD_];
__device__ __half  g_v [BHN*(size_t)S_*HD_];

// ---------------- PTX helpers ----------------
__device__ __forceinline__ uint32_t smem_u32(const void* p) {
    uint32_t a;
    asm("{ .reg .u64 t; cvta.to.shared.u64 t, %1; cvt.u32.u64 %0, t; }" : "=r"(a) : "l"(p));
    return a;
}

// PDL: signal dependents may launch / wait for predecessor completion
#define GRID_TRIGGER() asm volatile("griddepcontrol.launch_dependents;" ::: "memory")
#define GRID_WAIT()    asm volatile("griddepcontrol.wait;" ::: "memory")

// guaranteed single-MUFU exp2
__device__ __forceinline__ float ex2(float x) {
    float r;
    asm("ex2.approx.f32 %0, %1;" : "=f"(r) : "f"(x));
    return r;
}

#define MBARRIER_INIT(addr, cnt) \
    asm volatile("mbarrier.init.shared.b64 [%0], %1;" :: "r"(addr), "r"(cnt) : "memory")
#define MBARRIER_ARRIVE(addr) \
    asm volatile("mbarrier.arrive.shared.b64 _, [%0];" :: "r"(addr) : "memory")
#define MBARRIER_EXPECT_TX(addr, bytes) \
    asm volatile("mbarrier.arrive.expect_tx.shared.b64 _, [%0], %1;" :: "r"(addr), "r"(bytes) : "memory")

#define MBARRIER_WAIT_PARITY(addr, phase) do { \
    uint32_t _m = (addr); uint32_t _p = (phase); uint32_t _d; \
    asm volatile("{\n\t.reg .pred p;\n\t" \
        "mbarrier.try_wait.parity.acquire.cta.shared::cta.b64 p, [%1], %2;\n\t" \
        "selp.b32 %0, 1, 0, p;\n\t}" : "=r"(_d) : "r"(_m), "r"(_p) : "memory"); \
    if (!_d) { \
        asm volatile("{\n\t.reg .pred P1;\n\t" \
            "WL_%=:\n\t" \
            "mbarrier.try_wait.parity.acquire.cta.shared::cta.b64 P1, [%0], %1, 0x989680;\n\t" \
            "@P1 bra.uni WD_%=;\n\t" \
            "bra.uni WL_%=;\n\t" \
            "WD_%=:\n\t}" :: "r"(_m), "r"(_p) : "memory"); \
    } \
} while (0)

#define MBARRIER_WAIT_PARITY_RELAXED(addr, phase) do { \
    uint32_t _m = (addr); uint32_t _p = (phase); uint32_t _d; \
    asm volatile("{\n\t.reg .pred p;\n\t" \
        "mbarrier.try_wait.parity.relaxed.cta.shared::cta.b64 p, [%1], %2, 0x989680;\n\t" \
        "selp.b32 %0, 1, 0, p;\n\t}" : "=r"(_d) : "r"(_m), "r"(_p) : "memory"); \
    if (!_d) { \
        asm volatile("{\n\t.reg .pred P1;\n\t" \
            "WL_%=:\n\t" \
            "mbarrier.try_wait.parity.relaxed.cta.shared::cta.b64 P1, [%0], %1, 0x989680;\n\t" \
            "@P1 bra.uni WD_%=;\n\t" \
            "bra.uni WL_%=;\n\t" \
            "WD_%=:\n\t}" :: "r"(_m), "r"(_p) : "memory"); \
    } \
} while (0)

__device__ __forceinline__ void tma2d(uint32_t dst, const void* map, int x, int y, uint32_t mbar) {
    asm volatile("cp.async.bulk.tensor.2d.shared::cta.global.tile.mbarrier::complete_tx::bytes "
                 "[%0], [%1, {%2, %3}], [%4];"
                 :: "r"(dst), "l"(map), "r"(x), "r"(y), "r"(mbar) : "memory");
}

__device__ __forceinline__ void ldsm4(uint32_t* r, uint32_t addr) {
    asm volatile("ldmatrix.sync.aligned.m8n8.x4.shared.b16 {%0,%1,%2,%3}, [%4];"
                 : "=r"(r[0]), "=r"(r[1]), "=r"(r[2]), "=r"(r[3]) : "r"(addr));
}
__device__ __forceinline__ void ldsm4t(uint32_t* r, uint32_t addr) {
    asm volatile("ldmatrix.sync.aligned.m8n8.x4.trans.shared.b16 {%0,%1,%2,%3}, [%4];"
                 : "=r"(r[0]), "=r"(r[1]), "=r"(r[2]), "=r"(r[3]) : "r"(addr));
}

__device__ __forceinline__ void mma16816h(float* d, const uint32_t* a, const uint32_t* b) {
    asm volatile("mma.sync.aligned.m16n8k16.row.col.f32.f16.f16.f32 "
                 "{%0,%1,%2,%3}, {%4,%5,%6,%7}, {%8,%9}, {%0,%1,%2,%3};"
                 : "+f"(d[0]), "+f"(d[1]), "+f"(d[2]), "+f"(d[3])
                 : "r"(a[0]), "r"(a[1]), "r"(a[2]), "r"(a[3]), "r"(b[0]), "r"(b[1]));
}

__device__ __forceinline__ void cp16(uint32_t dst, const void* src) {
    asm volatile("cp.async.cg.shared.global [%0], [%1], 16;" :: "r"(dst), "l"(src) : "memory");
}
#define CP_COMMIT() asm volatile("cp.async.commit_group;" ::: "memory")
#define CP_WAIT(n)  asm volatile("cp.async.wait_group %0;" :: "n"(n) : "memory")

__device__ __forceinline__ float gelu_tanh(float u) {
    float c = 0.7978845608028654f * (u + 0.044715f * u * u * u);
    return 0.5f * u * (1.f + tanhf(c));
}

// ---------------- LayerNorm row body (fp16 out) ----------------
__device__ __forceinline__ void ln_row(const float* __restrict__ x, const float* __restrict__ w,
                                       const float* __restrict__ b, __half* __restrict__ y, int row)
{
    const int t = threadIdx.x;
    float4 v = ((const float4*)(x + (size_t)row * H_))[t];
    float s  = v.x + v.y + v.z + v.w;
    float sq = v.x*v.x + v.y*v.y + v.z*v.z + v.w*v.w;
    #pragma unroll
    for (int o = 16; o > 0; o >>= 1) {
        s  += __shfl_xor_sync(0xffffffffu, s,  o);
        sq += __shfl_xor_sync(0xffffffffu, sq, o);
    }
    __shared__ float ss[8], ssq[8];
    const int wid = t >> 5, lid = t & 31;
    if (lid == 0) { ss[wid] = s; ssq[wid] = sq; }
    __syncthreads();
    if (wid == 0) {
        float s2 = (lid < 8) ? ss[lid]  : 0.f;
        float q2 = (lid < 8) ? ssq[lid] : 0.f;
        #pragma unroll
        for (int o = 4; o > 0; o >>= 1) {
            s2 += __shfl_xor_sync(0xffffffffu, s2, o);
            q2 += __shfl_xor_sync(0xffffffffu, q2, o);
        }
        if (lid == 0) { ss[0] = s2; ssq[0] = q2; }
    }
    __syncthreads();
    const float mean = ss[0] * (1.f / H_);
    const float var  = ssq[0] * (1.f / H_) - mean * mean;
    const float rstd = rsqrtf(var + 1e-5f);
    float4 wv = ((const float4*)w)[t];
    float4 bv = ((const float4*)b)[t];
    float y0 = (v.x - mean) * rstd * wv.x + bv.x;
    float y1 = (v.y - mean) * rstd * wv.y + bv.y;
    float y2 = (v.z - mean) * rstd * wv.z + bv.z;
    float y3 = (v.w - mean) * rstd * wv.w + bv.w;
    __half2* yp = (__half2*)(y + (size_t)row * H_);
    yp[t*2]   = __floats2half2_rn(y0, y1);
    yp[t*2+1] = __floats2half2_rn(y2, y3);
}

__global__ void __launch_bounds__(256)
ln_h(const float* __restrict__ x, const float* __restrict__ w, const float* __restrict__ b,
     __half* __restrict__ y)
{
    GRID_TRIGGER();
    GRID_WAIT();
    ln_row(x, w, b, y, blockIdx.x);
}

// ---------------- fused: ln1 + all-weight fp32->fp16 convert ----------------
#define N4_QKV  (H3*H_/4)
#define N4_PROJ (H_*H_/4)
#define N4_FC1  (H4*H_/4)
#define N4_FC2  (H_*H4/4)
#define N4_ALL  (N4_QKV + N4_PROJ + N4_FC1 + N4_FC2)

__global__ void __launch_bounds__(256)
fused_prep(const float* __restrict__ x, const float* __restrict__ ln1w, const float* __restrict__ ln1b,
           __half* __restrict__ a16,
           const float* __restrict__ w0, const float* __restrict__ w1,
           const float* __restrict__ w2, const float* __restrict__ w3,
           __half* __restrict__ o0, __half* __restrict__ o1,
           __half* __restrict__ o2, __half* __restrict__ o3)
{
    GRID_TRIGGER();   // first kernel: no wait needed (inputs are external)
    if (blockIdx.x < ROWS) { ln_row(x, ln1w, ln1b, a16, blockIdx.x); return; }
    int i = (blockIdx.x - ROWS) * 256 + threadIdx.x;
    if (i >= N4_ALL) return;
    const float* s; __half* d; int k = i;
    if (k < N4_QKV)                    { s = w0; d = o0; }
    else if ((k -= N4_QKV)  < N4_PROJ) { s = w1; d = o1; }
    else if ((k -= N4_PROJ) < N4_FC1)  { s = w2; d = o2; }
    else { k -= N4_FC1;                  s = w3; d = o3; }
    float4 v = ((const float4*)s)[k];
    ((__half2*)d)[2*k]   = __floats2half2_rn(v.x, v.y);
    ((__half2*)d)[2*k+1] = __floats2half2_rn(v.z, v.w);
}

// ---------------- fp16 1-term GEMM (non-persistent, frozen) ----------------
// MODE 0: +bias -> scatter Q (scaled log2e/8), K, V (single fp16)
// MODE 1: gelu(+bias) -> fp16 C16
// MODE 2: +bias+resid -> fp32 C
static constexpr int SMEM_BYTES = 3*32768 + 1024;

template<int MODE>
__global__ void __launch_bounds__(288, 2)
gemm_tc(const __grid_constant__ CUtensorMap mA,
        const __grid_constant__ CUtensorMap mB,
        const float* __restrict__ bias, const float* __restrict__ resid,
        float* __restrict__ C, __half* __restrict__ C16,
        __half* __restrict__ qq, __half* __restrict__ kk, __half* __restrict__ vv,
        int N, int nc)
{
    extern __shared__ char smem[];
    const uint32_t sb  = smem_u32(smem);
    const uint32_t st0 = (sb + 64 + 1023) & ~1023u;
    const int tid = threadIdx.x;

    GRID_TRIGGER();
    // preamble (no predecessor data): mbarrier init + block sync — overlaps prior kernel's tail
    if (tid == 0) {
        #pragma unroll
        for (int i = 0; i < 3; i++) {
            MBARRIER_INIT(sb + 8*i, 1);
            MBARRIER_INIT(sb + 24 + 8*i, 8);
        }
    }
    __syncthreads();
    GRID_WAIT();      // predecessor outputs (A, B, resid) now visible

    const int bx = blockIdx.x, by = blockIdx.y;

    if (tid >= 256) {
        if (tid == 256) {
            for (int c = 0; c < nc; c++) {
                const int s = c % 3, r = c / 3;
                const uint32_t stg = st0 + s * 32768;
                if (r > 0) MBARRIER_WAIT_PARITY_RELAXED(sb + 24 + 8*s, (r - 1) & 1);
                MBARRIER_EXPECT_TX(sb + 8*s, 32768u);
                const int kx = c * 64;
                tma2d(stg,         &mA, kx, by * 128, sb + 8*s);
                tma2d(stg + 16384, &mB, kx, bx * 128, sb + 8*s);
            }
        }
        return;
    }

    const int lane = tid & 31;
    const int wm = (tid >> 5) >> 1;
    const int wn = (tid >> 5) & 1;

    const int arow0 = wm*32 + (lane & 15);
    const int acx   = lane >> 4;
    const int brow0 = wn*64 + (lane & 7) + ((lane >> 4) << 3);
    const int bcx   = (lane >> 3) & 1;

    float acc[2][8][4];
    #pragma unroll
    for (int i = 0; i < 2; i++)
        #pragma unroll
        for (int j = 0; j < 8; j++)
            #pragma unroll
            for (int q = 0; q < 4; q++) acc[i][j][q] = 0.f;

    for (int c = 0; c < nc; c++) {
        const int s = c % 3, r = c / 3;
        const uint32_t stg = st0 + s * 32768;
        MBARRIER_WAIT_PARITY(sb + 8*s, r & 1);

        #pragma unroll
        for (int ks = 0; ks < 4; ks++) {
            uint32_t af[2][4], bf[4][4];
            #pragma unroll
            for (int i = 0; i < 2; i++) {
                const int row = arow0 + i*16;
                const int cc  = 2*ks + acx;
                const uint32_t off = row*128 + (((uint32_t)(cc ^ (row & 7))) << 4);
                ldsm4(af[i], stg + off);
            }
            #pragma unroll
            for (int jt = 0; jt < 4; jt++) {
                const int row = brow0 + jt*16;
                const int cc  = 2*ks + bcx;
                const uint32_t off = row*128 + (((uint32_t)(cc ^ (row & 7))) << 4);
                ldsm4(bf[jt], stg + 16384 + off);
            }
            #pragma unroll
            for (int i = 0; i < 2; i++)
                #pragma unroll
                for (int j = 0; j < 8; j++)
                    mma16816h(acc[i][j], af[i], &bf[j>>1][(j&1)*2]);
        }
        if (lane == 0) MBARRIER_ARRIVE(sb + 24 + 8*s);
    }

    // ---- epilogue ----
    const int rbase = by*128 + wm*32 + (lane >> 2);
    const int cbase = bx*128 + wn*64 + (lane & 3)*2;
    #pragma unroll
    for (int j = 0; j < 8; j++) {
        const int col = cbase + j*8;
        const float bx0 = bias[col], bx1 = bias[col + 1];
        #pragma unroll
        for (int i = 0; i < 2; i++) {
            #pragma unroll
            for (int half = 0; half < 2; half++) {
                const int rowg = rbase + i*16 + half*8;
                float v0 = acc[i][j][half*2 + 0] + bx0;
                float v1 = acc[i][j][half*2 + 1] + bx1;
                if (MODE == 0) {
                    const int hh   = col / 192;
                    const int rem  = col - hh*192;
                    const int whch = rem >> 6;
                    const int d    = rem & 63;
                    const int ss   = rowg >> 1, bb = rowg & 1;
                    const size_t dst = ((size_t)(bb*16 + hh) * S_ + ss) * HD_ + d;
                    if (whch == 0) { v0 *= 0.18033688011f; v1 *= 0.18033688011f; }  // log2(e)/8
                    __half* dp = (whch == 0) ? qq : (whch == 1) ? kk : vv;
                    *(__half2*)&dp[dst] = __floats2half2_rn(v0, v1);
                } else if (MODE == 1) {
                    const size_t off = (size_t)rowg * N + col;
                    *(__half2*)&C16[off] = __floats2half2_rn(gelu_tanh(v0), gelu_tanh(v1));
                } else {
                    const size_t off = (size_t)rowg * N + col;
                    float2 rr = *(const float2*)&resid[off];
                    float2 o; o.x = v0 + rr.x; o.y = v1 + rr.y;
                    *(float2*)&C[off] = o;
                }
            }
        }
    }
}

// ---------------- Flash attention (fp16 HMMA, causal) ----------------
// BQ=128, BKV=64, 8 warps, 2 CTAs/SM. 1-term QK^T / PV, ex2.approx softmax.
// Single-sync pipeline; dual-path (branch-free vs sub-tile-skip) inner loops.
static constexpr int FLASH_SMEM = 48*1024 + 1024;

__global__ void __launch_bounds__(256, 2)
flash_mma(const __half* __restrict__ Q, const __half* __restrict__ K,
          const __half* __restrict__ V, __half* __restrict__ Out)
{
    extern __shared__ char smem[];
    const uint32_t sq  = (smem_u32(smem) + 1023) & ~1023u;
    const uint32_t skv = sq + 16384;   // + buf*16384; within: K 0, V 8192

    const int tid  = threadIdx.x;
    const int lane = tid & 31;
    const int wq   = tid >> 5;
    const int bhid = blockIdx.y;
    const int bb   = bhid >> 4;
    const int hh   = bhid & 15;
    const int qi   = (int)gridDim.x - 1 - (int)blockIdx.x;   // heavy tiles first
    const int q0   = qi << 7;
    const int ntiles = (q0 >> 6) + 2;

    const size_t hbase = (size_t)bhid * (S_ * HD_);

    GRID_TRIGGER();
    GRID_WAIT();      // Q/K/V come from the qkv GEMM

    // ---- prologue: Q + KV tile 0 ----
    #pragma unroll
    for (int i = 0; i < 4; i++) {
        const int idx = tid*4 + i;
        const int row = idx >> 3, cc = idx & 7;
        const uint32_t off = row*128 + (uint32_t)((cc ^ (row & 7)) << 4);
        const size_t src = hbase + (size_t)(q0 + row) * HD_ + cc*8;
        cp16(sq + off, Q + src);
    }
    #pragma unroll
    for (int i = 0; i < 2; i++) {
        const int idx = tid*2 + i;
        const int row = idx >> 3, cc = idx & 7;
        const uint32_t off = row*128 + (uint32_t)((cc ^ (row & 7)) << 4);
        const size_t src = hbase + (size_t)row * HD_ + cc*8;
        cp16(skv + off,        K + src);
        cp16(skv + 8192 + off, V + src);
    }
    CP_COMMIT();
    CP_WAIT(0);
    __syncthreads();

    // ---- Q fragments (registers) ----
    uint32_t qf[4][4];
    {
        const int row = wq*16 + (lane & 15);
        #pragma unroll
        for (int ks = 0; ks < 4; ks++) {
            const int cc = 2*ks + (lane >> 4);
            const uint32_t off = row*128 + (uint32_t)((cc ^ (row & 7)) << 4);
            ldsm4(qf[ks], sq + off);
        }
    }

    float m_i[2] = {-1e30f, -1e30f};
    float l_i[2] = {0.f, 0.f};
    float O[8][4];
    #pragma unroll
    for (int j = 0; j < 8; j++)
        #pragma unroll
        for (int q = 0; q < 4; q++) O[j][q] = 0.f;

    const int my_last_row = q0 + wq*16 + 15;

    for (int kt = 0; kt < ntiles; kt++) {
        const int t0 = kt << 6;
        if (kt > 0) {
            CP_WAIT(0);
            __syncthreads();
        }
        if (kt + 1 < ntiles) {
            const uint32_t stg = skv + ((kt+1) & 1) * 16384;
            const int tn0 = (kt+1) << 6;
            #pragma unroll
            for (int i = 0; i < 2; i++) {
                const int idx = tid*2 + i;
                const int row = idx >> 3, cc = idx & 7;
                const uint32_t off = row*128 + (uint32_t)((cc ^ (row & 7)) << 4);
                const size_t src = hbase + (size_t)(tn0 + row) * HD_ + cc*8;
                cp16(stg + off,        K + src);
                cp16(stg + 8192 + off, V + src);
            }
            CP_COMMIT();
        }

        if (t0 > my_last_row) continue;

        const uint32_t stg = skv + (kt & 1) * 16384;
        const uint32_t sk = stg, sv = stg + 8192;
        const bool full = (t0 + 48 <= my_last_row);

        float sc[8][4];
        #pragma unroll
        for (int j = 0; j < 8; j++)
            #pragma unroll
            for (int q = 0; q < 4; q++) sc[j][q] = 0.f;

        const int krow_b = (lane & 7) + ((lane >> 4) << 3);
        if (full) {
            #pragma unroll
            for (int ks = 0; ks < 4; ks++) {
                const int cc = 2*ks + ((lane >> 3) & 1);
                #pragma unroll
                for (int jt = 0; jt < 4; jt++) {
                    uint32_t bf[4];
                    const int row = jt*16 + krow_b;
                    const uint32_t off = row*128 + (uint32_t)((cc ^ (row & 7)) << 4);
                    ldsm4(bf, sk + off);
                    mma16816h(sc[2*jt],   qf[ks], &bf[0]);
                    mma16816h(sc[2*jt+1], qf[ks], &bf[2]);
                }
            }
        } else {
            for (int jt = 0; jt < 4; jt++) {
                if (t0 + jt*16 > my_last_row) break;
                const int row = jt*16 + krow_b;
                #pragma unroll
                for (int ks = 0; ks < 4; ks++) {
                    uint32_t bf[4];
                    const int cc = 2*ks + ((lane >> 3) & 1);
                    const uint32_t off = row*128 + (uint32_t)((cc ^ (row & 7)) << 4);
                    ldsm4(bf, sk + off);
                    mma16816h(sc[2*jt],   qf[ks], &bf[0]);
                    mma16816h(sc[2*jt+1], qf[ks], &bf[2]);
                }
            }
        }

        if (kt >= ntiles - 2) {
            const int r0g = q0 + wq*16 + (lane >> 2);
            #pragma unroll
            for (int j = 0; j < 8; j++) {
                const int c0 = t0 + j*8 + (lane & 3)*2;
                if (c0     > r0g)     sc[j][0] = -1e30f;
                if (c0 + 1 > r0g)     sc[j][1] = -1e30f;
                if (c0     > r0g + 8) sc[j][2] = -1e30f;
                if (c0 + 1 > r0g + 8) sc[j][3] = -1e30f;
            }
        }

        #pragma unroll
        for (int v = 0; v < 2; v++) {
            float rm = -1e30f;
            #pragma unroll
            for (int j = 0; j < 8; j++)
                rm = fmaxf(rm, fmaxf(sc[j][2*v], sc[j][2*v+1]));
            rm = fmaxf(rm, __shfl_xor_sync(0xffffffffu, rm, 1));
            rm = fmaxf(rm, __shfl_xor_sync(0xffffffffu, rm, 2));
            const float mnew = fmaxf(m_i[v], rm);
            const float corr = ex2(m_i[v] - mnew);
            float rs = 0.f;
            #pragma unroll
            for (int j = 0; j < 8; j++) {
                float p0 = ex2(sc[j][2*v]   - mnew);
                float p1 = ex2(sc[j][2*v+1] - mnew);
                sc[j][2*v] = p0; sc[j][2*v+1] = p1;
                rs += p0 + p1;
            }
            rs += __shfl_xor_sync(0xffffffffu, rs, 1);
            rs += __shfl_xor_sync(0xffffffffu, rs, 2);
            l_i[v] = l_i[v] * corr + rs;
            m_i[v] = mnew;
            #pragma unroll
            for (int j = 0; j < 8; j++) { O[j][2*v] *= corr; O[j][2*v+1] *= corr; }
        }

        const int vrow_b = (lane & 7) + (((lane >> 3) & 1) << 3);
        if (full) {
            #pragma unroll
            for (int kc = 0; kc < 4; kc++) {
                uint32_t pah[4];
                {
                    __half2 h2;
                    h2 = __floats2half2_rn(sc[2*kc][0],   sc[2*kc][1]);   pah[0] = *(uint32_t*)&h2;
                    h2 = __floats2half2_rn(sc[2*kc][2],   sc[2*kc][3]);   pah[1] = *(uint32_t*)&h2;
                    h2 = __floats2half2_rn(sc[2*kc+1][0], sc[2*kc+1][1]); pah[2] = *(uint32_t*)&h2;
                    h2 = __floats2half2_rn(sc[2*kc+1][2], sc[2*kc+1][3]); pah[3] = *(uint32_t*)&h2;
                }
                const int vrow = kc*16 + vrow_b;
                #pragma unroll
                for (int p = 0; p < 4; p++) {
                    const int cc = 2*p + (lane >> 4);
                    const uint32_t off = vrow*128 + (uint32_t)((cc ^ (vrow & 7)) << 4);
                    uint32_t vf[4];
                    ldsm4t(vf, sv + off);
                    mma16816h(O[2*p],   pah, &vf[0]);
                    mma16816h(O[2*p+1], pah, &vf[2]);
                }
            }
        } else {
            for (int kc = 0; kc < 4; kc++) {
                if (t0 + kc*16 > my_last_row) break;
                uint32_t pah[4];
                {
                    __half2 h2;
                    h2 = __floats2half2_rn(sc[2*kc][0],   sc[2*kc][1]);   pah[0] = *(uint32_t*)&h2;
                    h2 = __floats2half2_rn(sc[2*kc][2],   sc[2*kc][3]);   pah[1] = *(uint32_t*)&h2;
                    h2 = __floats2half2_rn(sc[2*kc+1][0], sc[2*kc+1][1]); pah[2] = *(uint32_t*)&h2;
                    h2 = __floats2half2_rn(sc[2*kc+1][2], sc[2*kc+1][3]); pah[3] = *(uint32_t*)&h2;
                }
                const int vrow = kc*16 + vrow_b;
                #pragma unroll
                for (int p = 0; p < 4; p++) {
                    const int cc = 2*p + (lane >> 4);
                    const uint32_t off = vrow*128 + (uint32_t)((cc ^ (vrow & 7)) << 4);
                    uint32_t vf[4];
                    ldsm4t(vf, sv + off);
                    mma16816h(O[2*p],   pah, &vf[0]);
                    mma16816h(O[2*p+1], pah, &vf[2]);
                }
            }
        }
    }

    // ---- epilogue: normalize + store fp16 ----
    #pragma unroll
    for (int v = 0; v < 2; v++) {
        const float inv = 1.f / l_i[v];
        const int srow = q0 + wq*16 + (lane >> 2) + v*8;
        const size_t base = ((size_t)srow * B_ + bb) * H_ + hh*HD_ + (lane & 3)*2;
        #pragma unroll
        for (int j = 0; j < 8; j++) {
            __half2 h2 = __floats2half2_rn(O[j][2*v] * inv, O[j][2*v+1] * inv);
            *(__half2*)&Out[base + j*8] = h2;
        }
    }
}

// ---------------- host ----------------
typedef CUresult (CUDAAPI *TMEncodeFn)(
    CUtensorMap*, CUtensorMapDataType, cuuint32_t, void*,
    const cuuint64_t*, const cuuint64_t*, const cuuint32_t*, const cuuint32_t*,
    CUtensorMapInterleave, CUtensorMapSwizzle, CUtensorMapL2promotion, CUtensorMapFloatOOBfill);

static void enc_map(TMEncodeFn fn, CUtensorMap* m, void* p, uint64_t rows, uint64_t k)
{
    cuuint64_t dims[2]    = {k, rows};
    cuuint64_t strides[1] = {k * 2};
    cuuint32_t box[2]     = {64, 128};
    cuuint32_t es[2]      = {1, 1};
    fn(m, CU_TENSOR_MAP_DATA_TYPE_FLOAT16, 2, p, dims, strides, box, es,
       CU_TENSOR_MAP_INTERLEAVE_NONE, CU_TENSOR_MAP_SWIZZLE_128B,
       CU_TENSOR_MAP_L2_PROMOTION_L2_128B, CU_TENSOR_MAP_FLOAT_OOB_FILL_NONE);
}

// launch helper with PDL attribute (graph-capturable)
template<typename F, typename... Args>
static void launch_pdl(F func, dim3 grid, dim3 block, size_t shmem, Args... args)
{
    cudaLaunchAttribute attr;
    attr.id = cudaLaunchAttributeProgrammaticStreamSerialization;
    attr.val.programmaticStreamSerializationAllowed = 1;
    cudaLaunchConfig_t cfg = {};
    cfg.gridDim = grid;
    cfg.blockDim = block;
    cfg.dynamicSmemBytes = shmem;
    cfg.stream = 0;
    cfg.attrs = &attr;
    cfg.numAttrs = 1;
    cudaLaunchKernelEx(&cfg, func, args...);
}

extern "C" void kernel_launch(void* const* d_in, const int* in_sizes, int n_in,
                              void* d_out, int out_size)
{
    const float* x     = (const float*)d_in[0];
    const float* ln1w  = (const float*)d_in[1];
    const float* ln1b  = (const float*)d_in[2];
    const float* wqkv  = (const float*)d_in[3];
    const float* bqkv  = (const float*)d_in[4];
    const float* wproj = (const float*)d_in[5];
    const float* bproj = (const float*)d_in[6];
    const float* ln2w  = (const float*)d_in[7];
    const float* ln2b  = (const float*)d_in[8];
    const float* wfc1  = (const float*)d_in[9];
    const float* bfc1  = (const float*)d_in[10];
    const float* wfc2  = (const float*)d_in[11];
    const float* bfc2  = (const float*)d_in[12];
    float* out = (float*)d_out;

    float *x1;
    __half *a16, *m16, *wq16, *wp16, *w116, *w216, *qq, *kk, *vv;
    cudaGetSymbolAddress((void**)&x1,   g_x1);
    cudaGetSymbolAddress((void**)&a16,  g_a);
    cudaGetSymbolAddress((void**)&m16,  g_m);
    cudaGetSymbolAddress((void**)&wq16, g_wqkv);
    cudaGetSymbolAddress((void**)&wp16, g_wproj);
    cudaGetSymbolAddress((void**)&w116, g_wfc1);
    cudaGetSymbolAddress((void**)&w216, g_wfc2);
    cudaGetSymbolAddress((void**)&qq,   g_q);
    cudaGetSymbolAddress((void**)&kk,   g_k);
    cudaGetSymbolAddress((void**)&vv,   g_v);

    TMEncodeFn enc = nullptr;
    cudaDriverEntryPointQueryResult qres;
    cudaGetDriverEntryPointByVersion("cuTensorMapEncodeTiled", (void**)&enc, 12000,
                                     cudaEnableDefault, &qres);

    cudaFuncSetAttribute((const void*)gemm_tc<0>, cudaFuncAttributeMaxDynamicSharedMemorySize, SMEM_BYTES);
    cudaFuncSetAttribute((const void*)gemm_tc<1>, cudaFuncAttributeMaxDynamicSharedMemorySize, SMEM_BYTES);
    cudaFuncSetAttribute((const void*)gemm_tc<2>, cudaFuncAttributeMaxDynamicSharedMemorySize, SMEM_BYTES);
    cudaFuncSetAttribute((const void*)flash_mma,  cudaFuncAttributeMaxDynamicSharedMemorySize, FLASH_SMEM);

    CUtensorMap mA, mB;

    // 0+1) fused: convert all weights fp16 + ln1 -> a16 (first kernel, normal launch)
    fused_prep<<<ROWS + (N4_ALL + 255)/256, 256>>>(x, ln1w, ln1b, a16,
        wqkv, wproj, wfc1, wfc2, wq16, wp16, w116, w216);
    // 2) qkv GEMM -> scatter Q/K/V : [4096,3072], K=1024
    enc_map(enc, &mA, a16, ROWS, H_);
    enc_map(enc, &mB, wq16, H3, H_);
    launch_pdl(gemm_tc<0>, dim3(H3/128, ROWS/128), dim3(288), (size_t)SMEM_BYTES,
        mA, mB, bqkv, (const float*)nullptr, (float*)nullptr, (__half*)nullptr,
        qq, kk, vv, (int)H3, (int)(H_/64));
    // 3) flash attention -> a16
    launch_pdl(flash_mma, dim3(S_/128, BHN), dim3(256), (size_t)FLASH_SMEM,
        (const __half*)qq, (const __half*)kk, (const __half*)vv, a16);
    // 4) x1 = x + attn @ wproj^T + b : [4096,1024], K=1024
    enc_map(enc, &mB, wp16, H_, H_);
    launch_pdl(gemm_tc<2>, dim3(H_/128, ROWS/128), dim3(288), (size_t)SMEM_BYTES,
        mA, mB, bproj, x, x1, (__half*)nullptr,
        (__half*)nullptr, (__half*)nullptr, (__half*)nullptr, (int)H_, (int)(H_/64));
    // 5) ln2 -> a16
    launch_pdl(ln_h, dim3(ROWS), dim3(256), (size_t)0, (const float*)x1, ln2w, ln2b, a16);
    // 6) mid = gelu(ln2 @ wfc1^T + b) -> m16 : [4096,4096], K=1024
    enc_map(enc, &mB, w116, H4, H_);
    launch_pdl(gemm_tc<1>, dim3(H4/128, ROWS/128), dim3(288), (size_t)SMEM_BYTES,
        mA, mB, bfc1, (const float*)nullptr, (float*)nullptr, m16,
        (__half*)nullptr, (__half*)nullptr, (__half*)nullptr, (int)H4, (int)(H_/64));
    // 7) out = x1 + mid @ wfc2^T + b : [4096,1024], K=4096
    enc_map(enc, &mA, m16, ROWS, H4);
    enc_map(enc, &mB, w216, H_, H4);
    launch_pdl(gemm_tc<2>, dim3(H_/128, ROWS/128), dim3(288), (size_t)SMEM_BYTES,
        mA, mB, bfc2, (const float*)x1, out, (__half*)nullptr,
        (__half*)nullptr, (__half*)nullptr, (__half*)nullptr, (int)H_, (int)(H4/64));
}

// round 16
// speedup vs baseline: 1.0556x; 1.0286x over previous
#include <cuda_runtime.h>
#include <cuda.h>
#include <cuda_fp16.h>
#include <math.h>
#include <stdint.h>

// Problem dims (fixed by reference)
#define S_    2048
#define B_    2
#define H_    1024
#define NH_   16
#define HD_   64
#define ROWS  (S_*B_)      // 4096
#define H3    (3*H_)       // 3072
#define H4    (4*H_)       // 4096
#define BHN   (B_*NH_)     // 32

// ---------------- scratch (no allocations allowed) ----------------
__device__ float   g_x1   [ROWS*(size_t)H_];
__device__ __half  g_a    [ROWS*(size_t)H_];
__device__ __half  g_m    [ROWS*(size_t)H4];
__device__ __half  g_wqkv [H3*(size_t)H_];
__device__ __half  g_wproj[H_*(size_t)H_];
__device__ __half  g_wfc1 [H4*(size_t)H_];
__device__ __half  g_wfc2 [H_*(size_t)H4];
__device__ __half  g_q [BHN*(size_t)S_*HD_];
__device__ __half  g_k [BHN*(size_t)S_*HD_];
__device__ __half  g_v [BHN*(size_t)S_*HD_];

// ---------------- PTX helpers ----------------
__device__ __forceinline__ uint32_t smem_u32(const void* p) {
    uint32_t a;
    asm("{ .reg .u64 t; cvta.to.shared.u64 t, %1; cvt.u32.u64 %0, t; }" : "=r"(a) : "l"(p));
    return a;
}

#define GRID_TRIGGER() asm volatile("griddepcontrol.launch_dependents;" ::: "memory")
#define GRID_WAIT()    asm volatile("griddepcontrol.wait;" ::: "memory")

__device__ __forceinline__ float ex2(float x) {
    float r;
    asm("ex2.approx.f32 %0, %1;" : "=f"(r) : "f"(x));
    return r;
}
// dual-half exp2: one MUFU op for two values
__device__ __forceinline__ uint32_t h2ex2(uint32_t x) {
    uint32_t r;
    asm("ex2.approx.f16x2 %0, %1;" : "=r"(r) : "r"(x));
    return r;
}

#define MBARRIER_INIT(addr, cnt) \
    asm volatile("mbarrier.init.shared.b64 [%0], %1;" :: "r"(addr), "r"(cnt) : "memory")
#define MBARRIER_ARRIVE(addr) \
    asm volatile("mbarrier.arrive.shared.b64 _, [%0];" :: "r"(addr) : "memory")
#define MBARRIER_EXPECT_TX(addr, bytes) \
    asm volatile("mbarrier.arrive.expect_tx.shared.b64 _, [%0], %1;" :: "r"(addr), "r"(bytes) : "memory")

#define MBARRIER_WAIT_PARITY(addr, phase) do { \
    uint32_t _m = (addr); uint32_t _p = (phase); uint32_t _d; \
    asm volatile("{\n\t.reg .pred p;\n\t" \
        "mbarrier.try_wait.parity.acquire.cta.shared::cta.b64 p, [%1], %2;\n\t" \
        "selp.b32 %0, 1, 0, p;\n\t}" : "=r"(_d) : "r"(_m), "r"(_p) : "memory"); \
    if (!_d) { \
        asm volatile("{\n\t.reg .pred P1;\n\t" \
            "WL_%=:\n\t" \
            "mbarrier.try_wait.parity.acquire.cta.shared::cta.b64 P1, [%0], %1, 0x989680;\n\t" \
            "@P1 bra.uni WD_%=;\n\t" \
            "bra.uni WL_%=;\n\t" \
            "WD_%=:\n\t}" :: "r"(_m), "r"(_p) : "memory"); \
    } \
} while (0)

#define MBARRIER_WAIT_PARITY_RELAXED(addr, phase) do { \
    uint32_t _m = (addr); uint32_t _p = (phase); uint32_t _d; \
    asm volatile("{\n\t.reg .pred p;\n\t" \
        "mbarrier.try_wait.parity.relaxed.cta.shared::cta.b64 p, [%1], %2, 0x989680;\n\t" \
        "selp.b32 %0, 1, 0, p;\n\t}" : "=r"(_d) : "r"(_m), "r"(_p) : "memory"); \
    if (!_d) { \
        asm volatile("{\n\t.reg .pred P1;\n\t" \
            "WL_%=:\n\t" \
            "mbarrier.try_wait.parity.relaxed.cta.shared::cta.b64 P1, [%0], %1, 0x989680;\n\t" \
            "@P1 bra.uni WD_%=;\n\t" \
            "bra.uni WL_%=;\n\t" \
            "WD_%=:\n\t}" :: "r"(_m), "r"(_p) : "memory"); \
    } \
} while (0)

__device__ __forceinline__ void tma2d(uint32_t dst, const void* map, int x, int y, uint32_t mbar) {
    asm volatile("cp.async.bulk.tensor.2d.shared::cta.global.tile.mbarrier::complete_tx::bytes "
                 "[%0], [%1, {%2, %3}], [%4];"
                 :: "r"(dst), "l"(map), "r"(x), "r"(y), "r"(mbar) : "memory");
}

__device__ __forceinline__ void ldsm4(uint32_t* r, uint32_t addr) {
    asm volatile("ldmatrix.sync.aligned.m8n8.x4.shared.b16 {%0,%1,%2,%3}, [%4];"
                 : "=r"(r[0]), "=r"(r[1]), "=r"(r[2]), "=r"(r[3]) : "r"(addr));
}
__device__ __forceinline__ void ldsm4t(uint32_t* r, uint32_t addr) {
    asm volatile("ldmatrix.sync.aligned.m8n8.x4.trans.shared.b16 {%0,%1,%2,%3}, [%4];"
                 : "=r"(r[0]), "=r"(r[1]), "=r"(r[2]), "=r"(r[3]) : "r"(addr));
}

__device__ __forceinline__ void mma16816h(float* d, const uint32_t* a, const uint32_t* b) {
    asm volatile("mma.sync.aligned.m16n8k16.row.col.f32.f16.f16.f32 "
                 "{%0,%1,%2,%3}, {%4,%5,%6,%7}, {%8,%9}, {%0,%1,%2,%3};"
                 : "+f"(d[0]), "+f"(d[1]), "+f"(d[2]), "+f"(d[3])
                 : "r"(a[0]), "r"(a[1]), "r"(a[2]), "r"(a[3]), "r"(b[0]), "r"(b[1]));
}

__device__ __forceinline__ void cp16(uint32_t dst, const void* src) {
    asm volatile("cp.async.cg.shared.global [%0], [%1], 16;" :: "r"(dst), "l"(src) : "memory");
}
#define CP_COMMIT() asm volatile("cp.async.commit_group;" ::: "memory")
#define CP_WAIT(n)  asm volatile("cp.async.wait_group %0;" :: "n"(n) : "memory")

__device__ __forceinline__ float gelu_tanh(float u) {
    float c = 0.7978845608028654f * (u + 0.044715f * u * u * u);
    return 0.5f * u * (1.f + tanhf(c));
}

// ---------------- LayerNorm row body (fp16 out) ----------------
__device__ __forceinline__ void ln_row(const float* __restrict__ x, const float* __restrict__ w,
                                       const float* __restrict__ b, __half* __restrict__ y, int row)
{
    const int t = threadIdx.x;
    float4 v = ((const float4*)(x + (size_t)row * H_))[t];
    float s  = v.x + v.y + v.z + v.w;
    float sq = v.x*v.x + v.y*v.y + v.z*v.z + v.w*v.w;
    #pragma unroll
    for (int o = 16; o > 0; o >>= 1) {
        s  += __shfl_xor_sync(0xffffffffu, s,  o);
        sq += __shfl_xor_sync(0xffffffffu, sq, o);
    }
    __shared__ float ss[8], ssq[8];
    const int wid = t >> 5, lid = t & 31;
    if (lid == 0) { ss[wid] = s; ssq[wid] = sq; }
    __syncthreads();
    if (wid == 0) {
        float s2 = (lid < 8) ? ss[lid]  : 0.f;
        float q2 = (lid < 8) ? ssq[lid] : 0.f;
        #pragma unroll
        for (int o = 4; o > 0; o >>= 1) {
            s2 += __shfl_xor_sync(0xffffffffu, s2, o);
            q2 += __shfl_xor_sync(0xffffffffu, q2, o);
        }
        if (lid == 0) { ss[0] = s2; ssq[0] = q2; }
    }
    __syncthreads();
    const float mean = ss[0] * (1.f / H_);
    const float var  = ssq[0] * (1.f / H_) - mean * mean;
    const float rstd = rsqrtf(var + 1e-5f);
    float4 wv = ((const float4*)w)[t];
    float4 bv = ((const float4*)b)[t];
    float y0 = (v.x - mean) * rstd * wv.x + bv.x;
    float y1 = (v.y - mean) * rstd * wv.y + bv.y;
    float y2 = (v.z - mean) * rstd * wv.z + bv.z;
    float y3 = (v.w - mean) * rstd * wv.w + bv.w;
    __half2* yp = (__half2*)(y + (size_t)row * H_);
    yp[t*2]   = __floats2half2_rn(y0, y1);
    yp[t*2+1] = __floats2half2_rn(y2, y3);
}

__global__ void __launch_bounds__(256)
ln_h(const float* __restrict__ x, const float* __restrict__ w, const float* __restrict__ b,
     __half* __restrict__ y)
{
    GRID_TRIGGER();
    GRID_WAIT();
    ln_row(x, w, b, y, blockIdx.x);
}

// ---------------- fused: ln1 + all-weight fp32->fp16 convert ----------------
#define N4_QKV  (H3*H_/4)
#define N4_PROJ (H_*H_/4)
#define N4_FC1  (H4*H_/4)
#define N4_FC2  (H_*H4/4)
#define N4_ALL  (N4_QKV + N4_PROJ + N4_FC1 + N4_FC2)

__global__ void __launch_bounds__(256)
fused_prep(const float* __restrict__ x, const float* __restrict__ ln1w, const float* __restrict__ ln1b,
           __half* __restrict__ a16,
           const float* __restrict__ w0, const float* __restrict__ w1,
           const float* __restrict__ w2, const float* __restrict__ w3,
           __half* __restrict__ o0, __half* __restrict__ o1,
           __half* __restrict__ o2, __half* __restrict__ o3)
{
    GRID_TRIGGER();
    if (blockIdx.x < ROWS) { ln_row(x, ln1w, ln1b, a16, blockIdx.x); return; }
    int i = (blockIdx.x - ROWS) * 256 + threadIdx.x;
    if (i >= N4_ALL) return;
    const float* s; __half* d; int k = i;
    if (k < N4_QKV)                    { s = w0; d = o0; }
    else if ((k -= N4_QKV)  < N4_PROJ) { s = w1; d = o1; }
    else if ((k -= N4_PROJ) < N4_FC1)  { s = w2; d = o2; }
    else { k -= N4_FC1;                  s = w3; d = o3; }
    float4 v = ((const float4*)s)[k];
    ((__half2*)d)[2*k]   = __floats2half2_rn(v.x, v.y);
    ((__half2*)d)[2*k+1] = __floats2half2_rn(v.z, v.w);
}

// ---------------- fp16 1-term GEMM (frozen at best config) ----------------
static constexpr int SMEM_BYTES = 3*32768 + 1024;

template<int MODE>
__global__ void __launch_bounds__(288, 2)
gemm_tc(const __grid_constant__ CUtensorMap mA,
        const __grid_constant__ CUtensorMap mB,
        const float* __restrict__ bias, const float* __restrict__ resid,
        float* __restrict__ C, __half* __restrict__ C16,
        __half* __restrict__ qq, __half* __restrict__ kk, __half* __restrict__ vv,
        int N, int nc)
{
    extern __shared__ char smem[];
    const uint32_t sb  = smem_u32(smem);
    const uint32_t st0 = (sb + 64 + 1023) & ~1023u;
    const int tid = threadIdx.x;

    GRID_TRIGGER();
    if (tid == 0) {
        #pragma unroll
        for (int i = 0; i < 3; i++) {
            MBARRIER_INIT(sb + 8*i, 1);
            MBARRIER_INIT(sb + 24 + 8*i, 8);
        }
    }
    __syncthreads();
    GRID_WAIT();

    const int bx = blockIdx.x, by = blockIdx.y;

    if (tid >= 256) {
        if (tid == 256) {
            for (int c = 0; c < nc; c++) {
                const int s = c % 3, r = c / 3;
                const uint32_t stg = st0 + s * 32768;
                if (r > 0) MBARRIER_WAIT_PARITY_RELAXED(sb + 24 + 8*s, (r - 1) & 1);
                MBARRIER_EXPECT_TX(sb + 8*s, 32768u);
                const int kx = c * 64;
                tma2d(stg,         &mA, kx, by * 128, sb + 8*s);
                tma2d(stg + 16384, &mB, kx, bx * 128, sb + 8*s);
            }
        }
        return;
    }

    const int lane = tid & 31;
    const int wm = (tid >> 5) >> 1;
    const int wn = (tid >> 5) & 1;

    const int arow0 = wm*32 + (lane & 15);
    const int acx   = lane >> 4;
    const int brow0 = wn*64 + (lane & 7) + ((lane >> 4) << 3);
    const int bcx   = (lane >> 3) & 1;

    float acc[2][8][4];
    #pragma unroll
    for (int i = 0; i < 2; i++)
        #pragma unroll
        for (int j = 0; j < 8; j++)
            #pragma unroll
            for (int q = 0; q < 4; q++) acc[i][j][q] = 0.f;

    for (int c = 0; c < nc; c++) {
        const int s = c % 3, r = c / 3;
        const uint32_t stg = st0 + s * 32768;
        MBARRIER_WAIT_PARITY(sb + 8*s, r & 1);

        #pragma unroll
        for (int ks = 0; ks < 4; ks++) {
            uint32_t af[2][4], bf[4][4];
            #pragma unroll
            for (int i = 0; i < 2; i++) {
                const int row = arow0 + i*16;
                const int cc  = 2*ks + acx;
                const uint32_t off = row*128 + (((uint32_t)(cc ^ (row & 7))) << 4);
                ldsm4(af[i], stg + off);
            }
            #pragma unroll
            for (int jt = 0; jt < 4; jt++) {
                const int row = brow0 + jt*16;
                const int cc  = 2*ks + bcx;
                const uint32_t off = row*128 + (((uint32_t)(cc ^ (row & 7))) << 4);
                ldsm4(bf[jt], stg + 16384 + off);
            }
            #pragma unroll
            for (int i = 0; i < 2; i++)
                #pragma unroll
                for (int j = 0; j < 8; j++)
                    mma16816h(acc[i][j], af[i], &bf[j>>1][(j&1)*2]);
        }
        if (lane == 0) MBARRIER_ARRIVE(sb + 24 + 8*s);
    }

    // ---- epilogue ----
    const int rbase = by*128 + wm*32 + (lane >> 2);
    const int cbase = bx*128 + wn*64 + (lane & 3)*2;
    #pragma unroll
    for (int j = 0; j < 8; j++) {
        const int col = cbase + j*8;
        const float bx0 = bias[col], bx1 = bias[col + 1];
        #pragma unroll
        for (int i = 0; i < 2; i++) {
            #pragma unroll
            for (int half = 0; half < 2; half++) {
                const int rowg = rbase + i*16 + half*8;
                float v0 = acc[i][j][half*2 + 0] + bx0;
                float v1 = acc[i][j][half*2 + 1] + bx1;
                if (MODE == 0) {
                    const int hh   = col / 192;
                    const int rem  = col - hh*192;
                    const int whch = rem >> 6;
                    const int d    = rem & 63;
                    const int ss   = rowg >> 1, bb = rowg & 1;
                    const size_t dst = ((size_t)(bb*16 + hh) * S_ + ss) * HD_ + d;
                    if (whch == 0) { v0 *= 0.18033688011f; v1 *= 0.18033688011f; }  // log2(e)/8
                    __half* dp = (whch == 0) ? qq : (whch == 1) ? kk : vv;
                    *(__half2*)&dp[dst] = __floats2half2_rn(v0, v1);
                } else if (MODE == 1) {
                    const size_t off = (size_t)rowg * N + col;
                    *(__half2*)&C16[off] = __floats2half2_rn(gelu_tanh(v0), gelu_tanh(v1));
                } else {
                    const size_t off = (size_t)rowg * N + col;
                    float2 rr = *(const float2*)&resid[off];
                    float2 o; o.x = v0 + rr.x; o.y = v1 + rr.y;
                    *(float2*)&C[off] = o;
                }
            }
        }
    }
}

// ---------------- Flash attention (fp16 HMMA, causal) ----------------
// f16x2 exp2 softmax; row-sum l via ones-column MMA (fp32, exactly matching
// the fp16 P used by PV). Single-sync pipeline; dual-path inner loops.
static constexpr int FLASH_SMEM = 48*1024 + 1024;

__global__ void __launch_bounds__(256, 2)
flash_mma(const __half* __restrict__ Q, const __half* __restrict__ K,
          const __half* __restrict__ V, __half* __restrict__ Out)
{
    extern __shared__ char smem[];
    const uint32_t sq  = (smem_u32(smem) + 1023) & ~1023u;
    const uint32_t skv = sq + 16384;   // + buf*16384; within: K 0, V 8192

    const int tid  = threadIdx.x;
    const int lane = tid & 31;
    const int wq   = tid >> 5;
    const int bhid = blockIdx.y;
    const int bb   = bhid >> 4;
    const int hh   = bhid & 15;
    const int qi   = (int)gridDim.x - 1 - (int)blockIdx.x;   // heavy tiles first
    const int q0   = qi << 7;
    const int ntiles = (q0 >> 6) + 2;

    const size_t hbase = (size_t)bhid * (S_ * HD_);

    GRID_TRIGGER();
    GRID_WAIT();

    // ---- prologue: Q + KV tile 0 ----
    #pragma unroll
    for (int i = 0; i < 4; i++) {
        const int idx = tid*4 + i;
        const int row = idx >> 3, cc = idx & 7;
        const uint32_t off = row*128 + (uint32_t)((cc ^ (row & 7)) << 4);
        const size_t src = hbase + (size_t)(q0 + row) * HD_ + cc*8;
        cp16(sq + off, Q + src);
    }
    #pragma unroll
    for (int i = 0; i < 2; i++) {
        const int idx = tid*2 + i;
        const int row = idx >> 3, cc = idx & 7;
        const uint32_t off = row*128 + (uint32_t)((cc ^ (row & 7)) << 4);
        const size_t src = hbase + (size_t)row * HD_ + cc*8;
        cp16(skv + off,        K + src);
        cp16(skv + 8192 + off, V + src);
    }
    CP_COMMIT();
    CP_WAIT(0);
    __syncthreads();

    // ---- Q fragments (registers) ----
    uint32_t qf[4][4];
    {
        const int row = wq*16 + (lane & 15);
        #pragma unroll
        for (int ks = 0; ks < 4; ks++) {
            const int cc = 2*ks + (lane >> 4);
            const uint32_t off = row*128 + (uint32_t)((cc ^ (row & 7)) << 4);
            ldsm4(qf[ks], sq + off);
        }
    }

    // ones-column B fragment for row-sum MMA: B[k][0]=1, other cols 0.
    // Lane i holds cols i/4 -> lanes 0..3 carry (1,1) pairs.
    uint32_t onesf[2];
    onesf[0] = onesf[1] = (lane < 4) ? 0x3C003C00u : 0u;

    float m_i[2] = {-1e30f, -1e30f};
    float Lacc[4] = {0.f, 0.f, 0.f, 0.f};   // l accumulator via MMA (col0 meaningful)
    float O[8][4];
    #pragma unroll
    for (int j = 0; j < 8; j++)
        #pragma unroll
        for (int q = 0; q < 4; q++) O[j][q] = 0.f;

    const int my_last_row = q0 + wq*16 + 15;

    for (int kt = 0; kt < ntiles; kt++) {
        const int t0 = kt << 6;
        if (kt > 0) {
            CP_WAIT(0);
            __syncthreads();
        }
        if (kt + 1 < ntiles) {
            const uint32_t stg = skv + ((kt+1) & 1) * 16384;
            const int tn0 = (kt+1) << 6;
            #pragma unroll
            for (int i = 0; i < 2; i++) {
                const int idx = tid*2 + i;
                const int row = idx >> 3, cc = idx & 7;
                const uint32_t off = row*128 + (uint32_t)((cc ^ (row & 7)) << 4);
                const size_t src = hbase + (size_t)(tn0 + row) * HD_ + cc*8;
                cp16(stg + off,        K + src);
                cp16(stg + 8192 + off, V + src);
            }
            CP_COMMIT();
        }

        if (t0 > my_last_row) continue;

        const uint32_t stg = skv + (kt & 1) * 16384;
        const uint32_t sk = stg, sv = stg + 8192;
        const bool full = (t0 + 48 <= my_last_row);

        // ---- scores S = Q K^T ----
        float sc[8][4];
        #pragma unroll
        for (int j = 0; j < 8; j++)
            #pragma unroll
            for (int q = 0; q < 4; q++) sc[j][q] = 0.f;

        const int krow_b = (lane & 7) + ((lane >> 4) << 3);
        if (full) {
            #pragma unroll
            for (int ks = 0; ks < 4; ks++) {
                const int cc = 2*ks + ((lane >> 3) & 1);
                #pragma unroll
                for (int jt = 0; jt < 4; jt++) {
                    uint32_t bf[4];
                    const int row = jt*16 + krow_b;
                    const uint32_t off = row*128 + (uint32_t)((cc ^ (row & 7)) << 4);
                    ldsm4(bf, sk + off);
                    mma16816h(sc[2*jt],   qf[ks], &bf[0]);
                    mma16816h(sc[2*jt+1], qf[ks], &bf[2]);
                }
            }
        } else {
            for (int jt = 0; jt < 4; jt++) {
                if (t0 + jt*16 > my_last_row) break;
                const int row = jt*16 + krow_b;
                #pragma unroll
                for (int ks = 0; ks < 4; ks++) {
                    uint32_t bf[4];
                    const int cc = 2*ks + ((lane >> 3) & 1);
                    const uint32_t off = row*128 + (uint32_t)((cc ^ (row & 7)) << 4);
                    ldsm4(bf, sk + off);
                    mma16816h(sc[2*jt],   qf[ks], &bf[0]);
                    mma16816h(sc[2*jt+1], qf[ks], &bf[2]);
                }
            }
        }

        // ---- causal mask (last two kv tiles only) ----
        if (kt >= ntiles - 2) {
            const int r0g = q0 + wq*16 + (lane >> 2);
            #pragma unroll
            for (int j = 0; j < 8; j++) {
                const int c0 = t0 + j*8 + (lane & 3)*2;
                if (c0     > r0g)     sc[j][0] = -1e30f;
                if (c0 + 1 > r0g)     sc[j][1] = -1e30f;
                if (c0     > r0g + 8) sc[j][2] = -1e30f;
                if (c0 + 1 > r0g + 8) sc[j][3] = -1e30f;
            }
        }

        // ---- online softmax: max-reduce, then pack+f16x2 exp ----
        float mnew[2], corr[2];
        #pragma unroll
        for (int v = 0; v < 2; v++) {
            float rm = -1e30f;
            #pragma unroll
            for (int j = 0; j < 8; j++)
                rm = fmaxf(rm, fmaxf(sc[j][2*v], sc[j][2*v+1]));
            rm = fmaxf(rm, __shfl_xor_sync(0xffffffffu, rm, 1));
            rm = fmaxf(rm, __shfl_xor_sync(0xffffffffu, rm, 2));
            mnew[v] = fmaxf(m_i[v], rm);
            corr[v] = ex2(m_i[v] - mnew[v]);
            m_i[v]  = mnew[v];
            #pragma unroll
            for (int j = 0; j < 8; j++) { O[j][2*v] *= corr[v]; O[j][2*v+1] *= corr[v]; }
        }
        Lacc[0] *= corr[0]; Lacc[1] *= corr[0];
        Lacc[2] *= corr[1]; Lacc[3] *= corr[1];

        uint32_t p2[8][2];
        #pragma unroll
        for (int j = 0; j < 8; j++) {
            #pragma unroll
            for (int v = 0; v < 2; v++) {
                __half2 d = __floats2half2_rn(sc[j][2*v] - mnew[v], sc[j][2*v+1] - mnew[v]);
                p2[j][v] = h2ex2(*(uint32_t*)&d);
            }
        }

        // ---- O += P V ; Lacc += P·ones (row sums, fp32 exact over fp16 P) ----
        const int vrow_b = (lane & 7) + (((lane >> 3) & 1) << 3);
        if (full) {
            #pragma unroll
            for (int kc = 0; kc < 4; kc++) {
                uint32_t pah[4] = { p2[2*kc][0], p2[2*kc][1], p2[2*kc+1][0], p2[2*kc+1][1] };
                mma16816h(Lacc, pah, onesf);
                const int vrow = kc*16 + vrow_b;
                #pragma unroll
                for (int p = 0; p < 4; p++) {
                    const int cc = 2*p + (lane >> 4);
                    const uint32_t off = vrow*128 + (uint32_t)((cc ^ (vrow & 7)) << 4);
                    uint32_t vf[4];
                    ldsm4t(vf, sv + off);
                    mma16816h(O[2*p],   pah, &vf[0]);
                    mma16816h(O[2*p+1], pah, &vf[2]);
                }
            }
        } else {
            for (int kc = 0; kc < 4; kc++) {
                if (t0 + kc*16 > my_last_row) break;
                uint32_t pah[4] = { p2[2*kc][0], p2[2*kc][1], p2[2*kc+1][0], p2[2*kc+1][1] };
                mma16816h(Lacc, pah, onesf);
                const int vrow = kc*16 + vrow_b;
                #pragma unroll
                for (int p = 0; p < 4; p++) {
                    const int cc = 2*p + (lane >> 4);
                    const uint32_t off = vrow*128 + (uint32_t)((cc ^ (vrow & 7)) << 4);
                    uint32_t vf[4];
                    ldsm4t(vf, sv + off);
                    mma16816h(O[2*p],   pah, &vf[0]);
                    mma16816h(O[2*p+1], pah, &vf[2]);
                }
            }
        }
    }

    // ---- epilogue: broadcast l within quad, normalize, store fp16 ----
    const float l0 = __shfl_sync(0xffffffffu, Lacc[0], lane & ~3);
    const float l1 = __shfl_sync(0xffffffffu, Lacc[2], lane & ~3);
    const float linv[2] = { 1.f / l0, 1.f / l1 };
    #pragma unroll
    for (int v = 0; v < 2; v++) {
        const float inv = linv[v];
        const int srow = q0 + wq*16 + (lane >> 2) + v*8;
        const size_t base = ((size_t)srow * B_ + bb) * H_ + hh*HD_ + (lane & 3)*2;
        #pragma unroll
        for (int j = 0; j < 8; j++) {
            __half2 h2 = __floats2half2_rn(O[j][2*v] * inv, O[j][2*v+1] * inv);
            *(__half2*)&Out[base + j*8] = h2;
        }
    }
}

// ---------------- host ----------------
typedef CUresult (CUDAAPI *TMEncodeFn)(
    CUtensorMap*, CUtensorMapDataType, cuuint32_t, void*,
    const cuuint64_t*, const cuuint64_t*, const cuuint32_t*, const cuuint32_t*,
    CUtensorMapInterleave, CUtensorMapSwizzle, CUtensorMapL2promotion, CUtensorMapFloatOOBfill);

static void enc_map(TMEncodeFn fn, CUtensorMap* m, void* p, uint64_t rows, uint64_t k)
{
    cuuint64_t dims[2]    = {k, rows};
    cuuint64_t strides[1] = {k * 2};
    cuuint32_t box[2]     = {64, 128};
    cuuint32_t es[2]      = {1, 1};
    fn(m, CU_TENSOR_MAP_DATA_TYPE_FLOAT16, 2, p, dims, strides, box, es,
       CU_TENSOR_MAP_INTERLEAVE_NONE, CU_TENSOR_MAP_SWIZZLE_128B,
       CU_TENSOR_MAP_L2_PROMOTION_L2_128B, CU_TENSOR_MAP_FLOAT_OOB_FILL_NONE);
}

template<typename F, typename... Args>
static void launch_pdl(F func, dim3 grid, dim3 block, size_t shmem, Args... args)
{
    cudaLaunchAttribute attr;
    attr.id = cudaLaunchAttributeProgrammaticStreamSerialization;
    attr.val.programmaticStreamSerializationAllowed = 1;
    cudaLaunchConfig_t cfg = {};
    cfg.gridDim = grid;
    cfg.blockDim = block;
    cfg.dynamicSmemBytes = shmem;
    cfg.stream = 0;
    cfg.attrs = &attr;
    cfg.numAttrs = 1;
    cudaLaunchKernelEx(&cfg, func, args...);
}

extern "C" void kernel_launch(void* const* d_in, const int* in_sizes, int n_in,
                              void* d_out, int out_size)
{
    const float* x     = (const float*)d_in[0];
    const float* ln1w  = (const float*)d_in[1];
    const float* ln1b  = (const float*)d_in[2];
    const float* wqkv  = (const float*)d_in[3];
    const float* bqkv  = (const float*)d_in[4];
    const float* wproj = (const float*)d_in[5];
    const float* bproj = (const float*)d_in[6];
    const float* ln2w  = (const float*)d_in[7];
    const float* ln2b  = (const float*)d_in[8];
    const float* wfc1  = (const float*)d_in[9];
    const float* bfc1  = (const float*)d_in[10];
    const float* wfc2  = (const float*)d_in[11];
    const float* bfc2  = (const float*)d_in[12];
    float* out = (float*)d_out;

    float *x1;
    __half *a16, *m16, *wq16, *wp16, *w116, *w216, *qq, *kk, *vv;
    cudaGetSymbolAddress((void**)&x1,   g_x1);
    cudaGetSymbolAddress((void**)&a16,  g_a);
    cudaGetSymbolAddress((void**)&m16,  g_m);
    cudaGetSymbolAddress((void**)&wq16, g_wqkv);
    cudaGetSymbolAddress((void**)&wp16, g_wproj);
    cudaGetSymbolAddress((void**)&w116, g_wfc1);
    cudaGetSymbolAddress((void**)&w216, g_wfc2);
    cudaGetSymbolAddress((void**)&qq,   g_q);
    cudaGetSymbolAddress((void**)&kk,   g_k);
    cudaGetSymbolAddress((void**)&vv,   g_v);

    TMEncodeFn enc = nullptr;
    cudaDriverEntryPointQueryResult qres;
    cudaGetDriverEntryPointByVersion("cuTensorMapEncodeTiled", (void**)&enc, 12000,
                                     cudaEnableDefault, &qres);

    cudaFuncSetAttribute((const void*)gemm_tc<0>, cudaFuncAttributeMaxDynamicSharedMemorySize, SMEM_BYTES);
    cudaFuncSetAttribute((const void*)gemm_tc<1>, cudaFuncAttributeMaxDynamicSharedMemorySize, SMEM_BYTES);
    cudaFuncSetAttribute((const void*)gemm_tc<2>, cudaFuncAttributeMaxDynamicSharedMemorySize, SMEM_BYTES);
    cudaFuncSetAttribute((const void*)flash_mma,  cudaFuncAttributeMaxDynamicSharedMemorySize, FLASH_SMEM);

    CUtensorMap mA, mB;

    // 0+1) fused: convert all weights fp16 + ln1 -> a16
    fused_prep<<<ROWS + (N4_ALL + 255)/256, 256>>>(x, ln1w, ln1b, a16,
        wqkv, wproj, wfc1, wfc2, wq16, wp16, w116, w216);
    // 2) qkv GEMM -> scatter Q/K/V : [4096,3072], K=1024
    enc_map(enc, &mA, a16, ROWS, H_);
    enc_map(enc, &mB, wq16, H3, H_);
    launch_pdl(gemm_tc<0>, dim3(H3/128, ROWS/128), dim3(288), (size_t)SMEM_BYTES,
        mA, mB, bqkv, (const float*)nullptr, (float*)nullptr, (__half*)nullptr,
        qq, kk, vv, (int)H3, (int)(H_/64));
    // 3) flash attention -> a16
    launch_pdl(flash_mma, dim3(S_/128, BHN), dim3(256), (size_t)FLASH_SMEM,
        (const __half*)qq, (const __half*)kk, (const __half*)vv, a16);
    // 4) x1 = x + attn @ wproj^T + b : [4096,1024], K=1024
    enc_map(enc, &mB, wp16, H_, H_);
    launch_pdl(gemm_tc<2>, dim3(H_/128, ROWS/128), dim3(288), (size_t)SMEM_BYTES,
        mA, mB, bproj, x, x1, (__half*)nullptr,
        (__half*)nullptr, (__half*)nullptr, (__half*)nullptr, (int)H_, (int)(H_/64));
    // 5) ln2 -> a16
    launch_pdl(ln_h, dim3(ROWS), dim3(256), (size_t)0, (const float*)x1, ln2w, ln2b, a16);
    // 6) mid = gelu(ln2 @ wfc1^T + b) -> m16 : [4096,4096], K=1024
    enc_map(enc, &mB, w116, H4, H_);
    launch_pdl(gemm_tc<1>, dim3(H4/128, ROWS/128), dim3(288), (size_t)SMEM_BYTES,
        mA, mB, bfc1, (const float*)nullptr, (float*)nullptr, m16,
        (__half*)nullptr, (__half*)nullptr, (__half*)nullptr, (int)H4, (int)(H_/64));
    // 7) out = x1 + mid @ wfc2^T + b : [4096,1024], K=4096
    enc_map(enc, &mA, m16, ROWS, H4);
    enc_map(enc, &mB, w216, H_, H4);
    launch_pdl(gemm_tc<2>, dim3(H_/128, ROWS/128), dim3(288), (size_t)SMEM_BYTES,
        mA, mB, bfc2, (const float*)x1, out, (__half*)nullptr,
        (__half*)nullptr, (__half*)nullptr, (__half*)nullptr, (int)H_, (int)(H4/64));
}

// round 17
// speedup vs baseline: 1.0603x; 1.0044x over previous
#include <cuda_runtime.h>
#include <cuda.h>
#include <cuda_fp16.h>
#include <math.h>
#include <stdint.h>

// Problem dims (fixed by reference)
#define S_    2048
#define B_    2
#define H_    1024
#define NH_   16
#define HD_   64
#define ROWS  (S_*B_)      // 4096
#define H3    (3*H_)       // 3072
#define H4    (4*H_)       // 4096
#define BHN   (B_*NH_)     // 32

// ---------------- scratch (no allocations allowed) ----------------
__device__ float   g_x1   [ROWS*(size_t)H_];
__device__ __half  g_a    [ROWS*(size_t)H_];
__device__ __half  g_m    [ROWS*(size_t)H4];
__device__ __half  g_wqkv [H3*(size_t)H_];
__device__ __half  g_wproj[H_*(size_t)H_];
__device__ __half  g_wfc1 [H4*(size_t)H_];
__device__ __half  g_wfc2 [H_*(size_t)H4];
__device__ __half  g_q [BHN*(size_t)S_*HD_];
__device__ __half  g_k [BHN*(size_t)S_*HD_];
__device__ __half  g_v [BHN*(size_t)S_*HD_];

// ---------------- PTX helpers ----------------
__device__ __forceinline__ uint32_t smem_u32(const void* p) {
    uint32_t a;
    asm("{ .reg .u64 t; cvta.to.shared.u64 t, %1; cvt.u32.u64 %0, t; }" : "=r"(a) : "l"(p));
    return a;
}

#define GRID_TRIGGER() asm volatile("griddepcontrol.launch_dependents;" ::: "memory")
#define GRID_WAIT()    asm volatile("griddepcontrol.wait;" ::: "memory")

__device__ __forceinline__ float ex2(float x) {
    float r;
    asm("ex2.approx.f32 %0, %1;" : "=f"(r) : "f"(x));
    return r;
}
// dual-half exp2: one MUFU op for two values
__device__ __forceinline__ uint32_t h2ex2(uint32_t x) {
    uint32_t r;
    asm("ex2.approx.f16x2 %0, %1;" : "=r"(r) : "r"(x));
    return r;
}
// packed fp32x2 helpers (sm_103a)
__device__ __forceinline__ uint64_t pack2(float a, float b) {
    uint64_t r; asm("mov.b64 %0, {%1,%2};" : "=l"(r) : "f"(a), "f"(b)); return r;
}
__device__ __forceinline__ void unpack2(uint64_t v, float& a, float& b) {
    asm("mov.b64 {%0,%1}, %2;" : "=f"(a), "=f"(b) : "l"(v));
}
__device__ __forceinline__ uint64_t addx2(uint64_t a, uint64_t b) {
    uint64_t r; asm("add.rn.f32x2 %0, %1, %2;" : "=l"(r) : "l"(a), "l"(b)); return r;
}
__device__ __forceinline__ uint64_t mulx2(uint64_t a, uint64_t b) {
    uint64_t r; asm("mul.rn.f32x2 %0, %1, %2;" : "=l"(r) : "l"(a), "l"(b)); return r;
}

#define MBARRIER_INIT(addr, cnt) \
    asm volatile("mbarrier.init.shared.b64 [%0], %1;" :: "r"(addr), "r"(cnt) : "memory")
#define MBARRIER_ARRIVE(addr) \
    asm volatile("mbarrier.arrive.shared.b64 _, [%0];" :: "r"(addr) : "memory")
#define MBARRIER_EXPECT_TX(addr, bytes) \
    asm volatile("mbarrier.arrive.expect_tx.shared.b64 _, [%0], %1;" :: "r"(addr), "r"(bytes) : "memory")

#define MBARRIER_WAIT_PARITY(addr, phase) do { \
    uint32_t _m = (addr); uint32_t _p = (phase); uint32_t _d; \
    asm volatile("{\n\t.reg .pred p;\n\t" \
        "mbarrier.try_wait.parity.acquire.cta.shared::cta.b64 p, [%1], %2;\n\t" \
        "selp.b32 %0, 1, 0, p;\n\t}" : "=r"(_d) : "r"(_m), "r"(_p) : "memory"); \
    if (!_d) { \
        asm volatile("{\n\t.reg .pred P1;\n\t" \
            "WL_%=:\n\t" \
            "mbarrier.try_wait.parity.acquire.cta.shared::cta.b64 P1, [%0], %1, 0x989680;\n\t" \
            "@P1 bra.uni WD_%=;\n\t" \
            "bra.uni WL_%=;\n\t" \
            "WD_%=:\n\t}" :: "r"(_m), "r"(_p) : "memory"); \
    } \
} while (0)

#define MBARRIER_WAIT_PARITY_RELAXED(addr, phase) do { \
    uint32_t _m = (addr); uint32_t _p = (phase); uint32_t _d; \
    asm volatile("{\n\t.reg .pred p;\n\t" \
        "mbarrier.try_wait.parity.relaxed.cta.shared::cta.b64 p, [%1], %2, 0x989680;\n\t" \
        "selp.b32 %0, 1, 0, p;\n\t}" : "=r"(_d) : "r"(_m), "r"(_p) : "memory"); \
    if (!_d) { \
        asm volatile("{\n\t.reg .pred P1;\n\t" \
            "WL_%=:\n\t" \
            "mbarrier.try_wait.parity.relaxed.cta.shared::cta.b64 P1, [%0], %1, 0x989680;\n\t" \
            "@P1 bra.uni WD_%=;\n\t" \
            "bra.uni WL_%=;\n\t" \
            "WD_%=:\n\t}" :: "r"(_m), "r"(_p) : "memory"); \
    } \
} while (0)

__device__ __forceinline__ void tma2d(uint32_t dst, const void* map, int x, int y, uint32_t mbar) {
    asm volatile("cp.async.bulk.tensor.2d.shared::cta.global.tile.mbarrier::complete_tx::bytes "
                 "[%0], [%1, {%2, %3}], [%4];"
                 :: "r"(dst), "l"(map), "r"(x), "r"(y), "r"(mbar) : "memory");
}

__device__ __forceinline__ void ldsm4(uint32_t* r, uint32_t addr) {
    asm volatile("ldmatrix.sync.aligned.m8n8.x4.shared.b16 {%0,%1,%2,%3}, [%4];"
                 : "=r"(r[0]), "=r"(r[1]), "=r"(r[2]), "=r"(r[3]) : "r"(addr));
}
__device__ __forceinline__ void ldsm4t(uint32_t* r, uint32_t addr) {
    asm volatile("ldmatrix.sync.aligned.m8n8.x4.trans.shared.b16 {%0,%1,%2,%3}, [%4];"
                 : "=r"(r[0]), "=r"(r[1]), "=r"(r[2]), "=r"(r[3]) : "r"(addr));
}

__device__ __forceinline__ void mma16816h(float* d, const uint32_t* a, const uint32_t* b) {
    asm volatile("mma.sync.aligned.m16n8k16.row.col.f32.f16.f16.f32 "
                 "{%0,%1,%2,%3}, {%4,%5,%6,%7}, {%8,%9}, {%0,%1,%2,%3};"
                 : "+f"(d[0]), "+f"(d[1]), "+f"(d[2]), "+f"(d[3])
                 : "r"(a[0]), "r"(a[1]), "r"(a[2]), "r"(a[3]), "r"(b[0]), "r"(b[1]));
}

__device__ __forceinline__ void cp16(uint32_t dst, const void* src) {
    asm volatile("cp.async.cg.shared.global [%0], [%1], 16;" :: "r"(dst), "l"(src) : "memory");
}
#define CP_COMMIT() asm volatile("cp.async.commit_group;" ::: "memory")
#define CP_WAIT(n)  asm volatile("cp.async.wait_group %0;" :: "n"(n) : "memory")

__device__ __forceinline__ float gelu_tanh(float u) {
    float c = 0.7978845608028654f * (u + 0.044715f * u * u * u);
    return 0.5f * u * (1.f + tanhf(c));
}

// ---------------- LayerNorm row body (fp16 out) ----------------
__device__ __forceinline__ void ln_row(const float* __restrict__ x, const float* __restrict__ w,
                                       const float* __restrict__ b, __half* __restrict__ y, int row)
{
    const int t = threadIdx.x;
    float4 v = ((const float4*)(x + (size_t)row * H_))[t];
    float s  = v.x + v.y + v.z + v.w;
    float sq = v.x*v.x + v.y*v.y + v.z*v.z + v.w*v.w;
    #pragma unroll
    for (int o = 16; o > 0; o >>= 1) {
        s  += __shfl_xor_sync(0xffffffffu, s,  o);
        sq += __shfl_xor_sync(0xffffffffu, sq, o);
    }
    __shared__ float ss[8], ssq[8];
    const int wid = t >> 5, lid = t & 31;
    if (lid == 0) { ss[wid] = s; ssq[wid] = sq; }
    __syncthreads();
    if (wid == 0) {
        float s2 = (lid < 8) ? ss[lid]  : 0.f;
        float q2 = (lid < 8) ? ssq[lid] : 0.f;
        #pragma unroll
        for (int o = 4; o > 0; o >>= 1) {
            s2 += __shfl_xor_sync(0xffffffffu, s2, o);
            q2 += __shfl_xor_sync(0xffffffffu, q2, o);
        }
        if (lid == 0) { ss[0] = s2; ssq[0] = q2; }
    }
    __syncthreads();
    const float mean = ss[0] * (1.f / H_);
    const float var  = ssq[0] * (1.f / H_) - mean * mean;
    const float rstd = rsqrtf(var + 1e-5f);
    float4 wv = ((const float4*)w)[t];
    float4 bv = ((const float4*)b)[t];
    float y0 = (v.x - mean) * rstd * wv.x + bv.x;
    float y1 = (v.y - mean) * rstd * wv.y + bv.y;
    float y2 = (v.z - mean) * rstd * wv.z + bv.z;
    float y3 = (v.w - mean) * rstd * wv.w + bv.w;
    __half2* yp = (__half2*)(y + (size_t)row * H_);
    yp[t*2]   = __floats2half2_rn(y0, y1);
    yp[t*2+1] = __floats2half2_rn(y2, y3);
}

__global__ void __launch_bounds__(256)
ln_h(const float* __restrict__ x, const float* __restrict__ w, const float* __restrict__ b,
     __half* __restrict__ y)
{
    GRID_TRIGGER();
    GRID_WAIT();
    ln_row(x, w, b, y, blockIdx.x);
}

// ---------------- fused: ln1 + all-weight fp32->fp16 convert ----------------
#define N4_QKV  (H3*H_/4)
#define N4_PROJ (H_*H_/4)
#define N4_FC1  (H4*H_/4)
#define N4_FC2  (H_*H4/4)
#define N4_ALL  (N4_QKV + N4_PROJ + N4_FC1 + N4_FC2)

__global__ void __launch_bounds__(256)
fused_prep(const float* __restrict__ x, const float* __restrict__ ln1w, const float* __restrict__ ln1b,
           __half* __restrict__ a16,
           const float* __restrict__ w0, const float* __restrict__ w1,
           const float* __restrict__ w2, const float* __restrict__ w3,
           __half* __restrict__ o0, __half* __restrict__ o1,
           __half* __restrict__ o2, __half* __restrict__ o3)
{
    GRID_TRIGGER();
    if (blockIdx.x < ROWS) { ln_row(x, ln1w, ln1b, a16, blockIdx.x); return; }
    int i = (blockIdx.x - ROWS) * 256 + threadIdx.x;
    if (i >= N4_ALL) return;
    const float* s; __half* d; int k = i;
    if (k < N4_QKV)                    { s = w0; d = o0; }
    else if ((k -= N4_QKV)  < N4_PROJ) { s = w1; d = o1; }
    else if ((k -= N4_PROJ) < N4_FC1)  { s = w2; d = o2; }
    else { k -= N4_FC1;                  s = w3; d = o3; }
    float4 v = ((const float4*)s)[k];
    ((__half2*)d)[2*k]   = __floats2half2_rn(v.x, v.y);
    ((__half2*)d)[2*k+1] = __floats2half2_rn(v.z, v.w);
}

// ---------------- fp16 1-term GEMM (frozen at best config) ----------------
static constexpr int SMEM_BYTES = 3*32768 + 1024;

template<int MODE>
__global__ void __launch_bounds__(288, 2)
gemm_tc(const __grid_constant__ CUtensorMap mA,
        const __grid_constant__ CUtensorMap mB,
        const float* __restrict__ bias, const float* __restrict__ resid,
        float* __restrict__ C, __half* __restrict__ C16,
        __half* __restrict__ qq, __half* __restrict__ kk, __half* __restrict__ vv,
        int N, int nc)
{
    extern __shared__ char smem[];
    const uint32_t sb  = smem_u32(smem);
    const uint32_t st0 = (sb + 64 + 1023) & ~1023u;
    const int tid = threadIdx.x;

    GRID_TRIGGER();
    if (tid == 0) {
        #pragma unroll
        for (int i = 0; i < 3; i++) {
            MBARRIER_INIT(sb + 8*i, 1);
            MBARRIER_INIT(sb + 24 + 8*i, 8);
        }
    }
    __syncthreads();
    GRID_WAIT();

    const int bx = blockIdx.x, by = blockIdx.y;

    if (tid >= 256) {
        if (tid == 256) {
            for (int c = 0; c < nc; c++) {
                const int s = c % 3, r = c / 3;
                const uint32_t stg = st0 + s * 32768;
                if (r > 0) MBARRIER_WAIT_PARITY_RELAXED(sb + 24 + 8*s, (r - 1) & 1);
                MBARRIER_EXPECT_TX(sb + 8*s, 32768u);
                const int kx = c * 64;
                tma2d(stg,         &mA, kx, by * 128, sb + 8*s);
                tma2d(stg + 16384, &mB, kx, bx * 128, sb + 8*s);
            }
        }
        return;
    }

    const int lane = tid & 31;
    const int wm = (tid >> 5) >> 1;
    const int wn = (tid >> 5) & 1;

    const int arow0 = wm*32 + (lane & 15);
    const int acx   = lane >> 4;
    const int brow0 = wn*64 + (lane & 7) + ((lane >> 4) << 3);
    const int bcx   = (lane >> 3) & 1;

    float acc[2][8][4];
    #pragma unroll
    for (int i = 0; i < 2; i++)
        #pragma unroll
        for (int j = 0; j < 8; j++)
            #pragma unroll
            for (int q = 0; q < 4; q++) acc[i][j][q] = 0.f;

    for (int c = 0; c < nc; c++) {
        const int s = c % 3, r = c / 3;
        const uint32_t stg = st0 + s * 32768;
        MBARRIER_WAIT_PARITY(sb + 8*s, r & 1);

        #pragma unroll
        for (int ks = 0; ks < 4; ks++) {
            uint32_t af[2][4], bf[4][4];
            #pragma unroll
            for (int i = 0; i < 2; i++) {
                const int row = arow0 + i*16;
                const int cc  = 2*ks + acx;
                const uint32_t off = row*128 + (((uint32_t)(cc ^ (row & 7))) << 4);
                ldsm4(af[i], stg + off);
            }
            #pragma unroll
            for (int jt = 0; jt < 4; jt++) {
                const int row = brow0 + jt*16;
                const int cc  = 2*ks + bcx;
                const uint32_t off = row*128 + (((uint32_t)(cc ^ (row & 7))) << 4);
                ldsm4(bf[jt], stg + 16384 + off);
            }
            #pragma unroll
            for (int i = 0; i < 2; i++)
                #pragma unroll
                for (int j = 0; j < 8; j++)
                    mma16816h(acc[i][j], af[i], &bf[j>>1][(j&1)*2]);
        }
        if (lane == 0) MBARRIER_ARRIVE(sb + 24 + 8*s);
    }

    // ---- epilogue ----
    const int rbase = by*128 + wm*32 + (lane >> 2);
    const int cbase = bx*128 + wn*64 + (lane & 3)*2;
    #pragma unroll
    for (int j = 0; j < 8; j++) {
        const int col = cbase + j*8;
        const float bx0 = bias[col], bx1 = bias[col + 1];
        #pragma unroll
        for (int i = 0; i < 2; i++) {
            #pragma unroll
            for (int half = 0; half < 2; half++) {
                const int rowg = rbase + i*16 + half*8;
                float v0 = acc[i][j][half*2 + 0] + bx0;
                float v1 = acc[i][j][half*2 + 1] + bx1;
                if (MODE == 0) {
                    const int hh   = col / 192;
                    const int rem  = col - hh*192;
                    const int whch = rem >> 6;
                    const int d    = rem & 63;
                    const int ss   = rowg >> 1, bb = rowg & 1;
                    const size_t dst = ((size_t)(bb*16 + hh) * S_ + ss) * HD_ + d;
                    if (whch == 0) { v0 *= 0.18033688011f; v1 *= 0.18033688011f; }  // log2(e)/8
                    __half* dp = (whch == 0) ? qq : (whch == 1) ? kk : vv;
                    *(__half2*)&dp[dst] = __floats2half2_rn(v0, v1);
                } else if (MODE == 1) {
                    const size_t off = (size_t)rowg * N + col;
                    *(__half2*)&C16[off] = __floats2half2_rn(gelu_tanh(v0), gelu_tanh(v1));
                } else {
                    const size_t off = (size_t)rowg * N + col;
                    float2 rr = *(const float2*)&resid[off];
                    float2 o; o.x = v0 + rr.x; o.y = v1 + rr.y;
                    *(float2*)&C[off] = o;
                }
            }
        }
    }
}

// ---------------- Flash attention (fp16 HMMA, causal) ----------------
// f16x2 exp2 softmax; row-sum l via ones-column MMA; packed f32x2 for the
// score-minus-max and O-rescale bookkeeping. Single-sync pipeline; dual-path.
static constexpr int FLASH_SMEM = 48*1024 + 1024;

__global__ void __launch_bounds__(256, 2)
flash_mma(const __half* __restrict__ Q, const __half* __restrict__ K,
          const __half* __restrict__ V, __half* __restrict__ Out)
{
    extern __shared__ char smem[];
    const uint32_t sq  = (smem_u32(smem) + 1023) & ~1023u;
    const uint32_t skv = sq + 16384;   // + buf*16384; within: K 0, V 8192

    const int tid  = threadIdx.x;
    const int lane = tid & 31;
    const int wq   = tid >> 5;
    const int bhid = blockIdx.y;
    const int bb   = bhid >> 4;
    const int hh   = bhid & 15;
    const int qi   = (int)gridDim.x - 1 - (int)blockIdx.x;   // heavy tiles first
    const int q0   = qi << 7;
    const int ntiles = (q0 >> 6) + 2;

    const size_t hbase = (size_t)bhid * (S_ * HD_);

    GRID_TRIGGER();
    GRID_WAIT();

    // ---- prologue: Q + KV tile 0 ----
    #pragma unroll
    for (int i = 0; i < 4; i++) {
        const int idx = tid*4 + i;
        const int row = idx >> 3, cc = idx & 7;
        const uint32_t off = row*128 + (uint32_t)((cc ^ (row & 7)) << 4);
        const size_t src = hbase + (size_t)(q0 + row) * HD_ + cc*8;
        cp16(sq + off, Q + src);
    }
    #pragma unroll
    for (int i = 0; i < 2; i++) {
        const int idx = tid*2 + i;
        const int row = idx >> 3, cc = idx & 7;
        const uint32_t off = row*128 + (uint32_t)((cc ^ (row & 7)) << 4);
        const size_t src = hbase + (size_t)row * HD_ + cc*8;
        cp16(skv + off,        K + src);
        cp16(skv + 8192 + off, V + src);
    }
    CP_COMMIT();
    CP_WAIT(0);
    __syncthreads();

    // ---- Q fragments (registers) ----
    uint32_t qf[4][4];
    {
        const int row = wq*16 + (lane & 15);
        #pragma unroll
        for (int ks = 0; ks < 4; ks++) {
            const int cc = 2*ks + (lane >> 4);
            const uint32_t off = row*128 + (uint32_t)((cc ^ (row & 7)) << 4);
            ldsm4(qf[ks], sq + off);
        }
    }

    // ones-column B fragment for row-sum MMA
    uint32_t onesf[2];
    onesf[0] = onesf[1] = (lane < 4) ? 0x3C003C00u : 0u;

    float m_i[2] = {-1e30f, -1e30f};
    float Lacc[4] = {0.f, 0.f, 0.f, 0.f};
    float O[8][4];
    #pragma unroll
    for (int j = 0; j < 8; j++)
        #pragma unroll
        for (int q = 0; q < 4; q++) O[j][q] = 0.f;

    const int my_last_row = q0 + wq*16 + 15;

    for (int kt = 0; kt < ntiles; kt++) {
        const int t0 = kt << 6;
        if (kt > 0) {
            CP_WAIT(0);
            __syncthreads();
        }
        if (kt + 1 < ntiles) {
            const uint32_t stg = skv + ((kt+1) & 1) * 16384;
            const int tn0 = (kt+1) << 6;
            #pragma unroll
            for (int i = 0; i < 2; i++) {
                const int idx = tid*2 + i;
                const int row = idx >> 3, cc = idx & 7;
                const uint32_t off = row*128 + (uint32_t)((cc ^ (row & 7)) << 4);
                const size_t src = hbase + (size_t)(tn0 + row) * HD_ + cc*8;
                cp16(stg + off,        K + src);
                cp16(stg + 8192 + off, V + src);
            }
            CP_COMMIT();
        }

        if (t0 > my_last_row) continue;

        const uint32_t stg = skv + (kt & 1) * 16384;
        const uint32_t sk = stg, sv = stg + 8192;
        const bool full = (t0 + 48 <= my_last_row);

        // ---- scores S = Q K^T ----
        float sc[8][4];
        #pragma unroll
        for (int j = 0; j < 8; j++)
            #pragma unroll
            for (int q = 0; q < 4; q++) sc[j][q] = 0.f;

        const int krow_b = (lane & 7) + ((lane >> 4) << 3);
        if (full) {
            #pragma unroll
            for (int ks = 0; ks < 4; ks++) {
                const int cc = 2*ks + ((lane >> 3) & 1);
                #pragma unroll
                for (int jt = 0; jt < 4; jt++) {
                    uint32_t bf[4];
                    const int row = jt*16 + krow_b;
                    const uint32_t off = row*128 + (uint32_t)((cc ^ (row & 7)) << 4);
                    ldsm4(bf, sk + off);
                    mma16816h(sc[2*jt],   qf[ks], &bf[0]);
                    mma16816h(sc[2*jt+1], qf[ks], &bf[2]);
                }
            }
        } else {
            for (int jt = 0; jt < 4; jt++) {
                if (t0 + jt*16 > my_last_row) break;
                const int row = jt*16 + krow_b;
                #pragma unroll
                for (int ks = 0; ks < 4; ks++) {
                    uint32_t bf[4];
                    const int cc = 2*ks + ((lane >> 3) & 1);
                    const uint32_t off = row*128 + (uint32_t)((cc ^ (row & 7)) << 4);
                    ldsm4(bf, sk + off);
                    mma16816h(sc[2*jt],   qf[ks], &bf[0]);
                    mma16816h(sc[2*jt+1], qf[ks], &bf[2]);
                }
            }
        }

        // ---- causal mask (last two kv tiles only) ----
        if (kt >= ntiles - 2) {
            const int r0g = q0 + wq*16 + (lane >> 2);
            #pragma unroll
            for (int j = 0; j < 8; j++) {
                const int c0 = t0 + j*8 + (lane & 3)*2;
                if (c0     > r0g)     sc[j][0] = -1e30f;
                if (c0 + 1 > r0g)     sc[j][1] = -1e30f;
                if (c0     > r0g + 8) sc[j][2] = -1e30f;
                if (c0 + 1 > r0g + 8) sc[j][3] = -1e30f;
            }
        }

        // ---- online softmax: max-reduce, packed subtract, f16x2 exp ----
        float mnew[2], corr[2];
        #pragma unroll
        for (int v = 0; v < 2; v++) {
            float rm = -1e30f;
            #pragma unroll
            for (int j = 0; j < 8; j++)
                rm = fmaxf(rm, fmaxf(sc[j][2*v], sc[j][2*v+1]));
            rm = fmaxf(rm, __shfl_xor_sync(0xffffffffu, rm, 1));
            rm = fmaxf(rm, __shfl_xor_sync(0xffffffffu, rm, 2));
            mnew[v] = fmaxf(m_i[v], rm);
            corr[v] = ex2(m_i[v] - mnew[v]);
            m_i[v]  = mnew[v];
            // O rescale via packed f32x2 (accumulator pairs are register-adjacent)
            const uint64_t c2 = pack2(corr[v], corr[v]);
            #pragma unroll
            for (int j = 0; j < 8; j++) {
                uint64_t o2 = mulx2(pack2(O[j][2*v], O[j][2*v+1]), c2);
                unpack2(o2, O[j][2*v], O[j][2*v+1]);
            }
        }
        Lacc[0] *= corr[0]; Lacc[1] *= corr[0];
        Lacc[2] *= corr[1]; Lacc[3] *= corr[1];

        uint32_t p2[8][2];
        {
            const uint64_t nm0 = pack2(-mnew[0], -mnew[0]);
            const uint64_t nm1 = pack2(-mnew[1], -mnew[1]);
            #pragma unroll
            for (int j = 0; j < 8; j++) {
                float a0, a1, b0, b1;
                unpack2(addx2(pack2(sc[j][0], sc[j][1]), nm0), a0, a1);
                unpack2(addx2(pack2(sc[j][2], sc[j][3]), nm1), b0, b1);
                __half2 d0 = __floats2half2_rn(a0, a1);
                __half2 d1 = __floats2half2_rn(b0, b1);
                p2[j][0] = h2ex2(*(uint32_t*)&d0);
                p2[j][1] = h2ex2(*(uint32_t*)&d1);
            }
        }

        // ---- O += P V ; Lacc += P·ones ----
        const int vrow_b = (lane & 7) + (((lane >> 3) & 1) << 3);
        if (full) {
            #pragma unroll
            for (int kc = 0; kc < 4; kc++) {
                uint32_t pah[4] = { p2[2*kc][0], p2[2*kc][1], p2[2*kc+1][0], p2[2*kc+1][1] };
                mma16816h(Lacc, pah, onesf);
                const int vrow = kc*16 + vrow_b;
                #pragma unroll
                for (int p = 0; p < 4; p++) {
                    const int cc = 2*p + (lane >> 4);
                    const uint32_t off = vrow*128 + (uint32_t)((cc ^ (vrow & 7)) << 4);
                    uint32_t vf[4];
                    ldsm4t(vf, sv + off);
                    mma16816h(O[2*p],   pah, &vf[0]);
                    mma16816h(O[2*p+1], pah, &vf[2]);
                }
            }
        } else {
            for (int kc = 0; kc < 4; kc++) {
                if (t0 + kc*16 > my_last_row) break;
                uint32_t pah[4] = { p2[2*kc][0], p2[2*kc][1], p2[2*kc+1][0], p2[2*kc+1][1] };
                mma16816h(Lacc, pah, onesf);
                const int vrow = kc*16 + vrow_b;
                #pragma unroll
                for (int p = 0; p < 4; p++) {
                    const int cc = 2*p + (lane >> 4);
                    const uint32_t off = vrow*128 + (uint32_t)((cc ^ (vrow & 7)) << 4);
                    uint32_t vf[4];
                    ldsm4t(vf, sv + off);
                    mma16816h(O[2*p],   pah, &vf[0]);
                    mma16816h(O[2*p+1], pah, &vf[2]);
                }
            }
        }
    }

    // ---- epilogue: broadcast l within quad, packed normalize, store fp16 ----
    const float l0 = __shfl_sync(0xffffffffu, Lacc[0], lane & ~3);
    const float l1 = __shfl_sync(0xffffffffu, Lacc[2], lane & ~3);
    const float linv[2] = { 1.f / l0, 1.f / l1 };
    #pragma unroll
    for (int v = 0; v < 2; v++) {
        const uint64_t i2 = pack2(linv[v], linv[v]);
        const int srow = q0 + wq*16 + (lane >> 2) + v*8;
        const size_t base = ((size_t)srow * B_ + bb) * H_ + hh*HD_ + (lane & 3)*2;
        #pragma unroll
        for (int j = 0; j < 8; j++) {
            float o0, o1;
            unpack2(mulx2(pack2(O[j][2*v], O[j][2*v+1]), i2), o0, o1);
            __half2 h2 = __floats2half2_rn(o0, o1);
            *(__half2*)&Out[base + j*8] = h2;
        }
    }
}

// ---------------- host ----------------
typedef CUresult (CUDAAPI *TMEncodeFn)(
    CUtensorMap*, CUtensorMapDataType, cuuint32_t, void*,
    const cuuint64_t*, const cuuint64_t*, const cuuint32_t*, const cuuint32_t*,
    CUtensorMapInterleave, CUtensorMapSwizzle, CUtensorMapL2promotion, CUtensorMapFloatOOBfill);

static void enc_map(TMEncodeFn fn, CUtensorMap* m, void* p, uint64_t rows, uint64_t k)
{
    cuuint64_t dims[2]    = {k, rows};
    cuuint64_t strides[1] = {k * 2};
    cuuint32_t box[2]     = {64, 128};
    cuuint32_t es[2]      = {1, 1};
    fn(m, CU_TENSOR_MAP_DATA_TYPE_FLOAT16, 2, p, dims, strides, box, es,
       CU_TENSOR_MAP_INTERLEAVE_NONE, CU_TENSOR_MAP_SWIZZLE_128B,
       CU_TENSOR_MAP_L2_PROMOTION_L2_128B, CU_TENSOR_MAP_FLOAT_OOB_FILL_NONE);
}

template<typename F, typename... Args>
static void launch_pdl(F func, dim3 grid, dim3 block, size_t shmem, Args... args)
{
    cudaLaunchAttribute attr;
    attr.id = cudaLaunchAttributeProgrammaticStreamSerialization;
    attr.val.programmaticStreamSerializationAllowed = 1;
    cudaLaunchConfig_t cfg = {};
    cfg.gridDim = grid;
    cfg.blockDim = block;
    cfg.dynamicSmemBytes = shmem;
    cfg.stream = 0;
    cfg.attrs = &attr;
    cfg.numAttrs = 1;
    cudaLaunchKernelEx(&cfg, func, args...);
}

extern "C" void kernel_launch(void* const* d_in, const int* in_sizes, int n_in,
                              void* d_out, int out_size)
{
    const float* x     = (const float*)d_in[0];
    const float* ln1w  = (const float*)d_in[1];
    const float* ln1b  = (const float*)d_in[2];
    const float* wqkv  = (const float*)d_in[3];
    const float* bqkv  = (const float*)d_in[4];
    const float* wproj = (const float*)d_in[5];
    const float* bproj = (const float*)d_in[6];
    const float* ln2w  = (const float*)d_in[7];
    const float* ln2b  = (const float*)d_in[8];
    const float* wfc1  = (const float*)d_in[9];
    const float* bfc1  = (const float*)d_in[10];
    const float* wfc2  = (const float*)d_in[11];
    const float* bfc2  = (const float*)d_in[12];
    float* out = (float*)d_out;

    float *x1;
    __half *a16, *m16, *wq16, *wp16, *w116, *w216, *qq, *kk, *vv;
    cudaGetSymbolAddress((void**)&x1,   g_x1);
    cudaGetSymbolAddress((void**)&a16,  g_a);
    cudaGetSymbolAddress((void**)&m16,  g_m);
    cudaGetSymbolAddress((void**)&wq16, g_wqkv);
    cudaGetSymbolAddress((void**)&wp16, g_wproj);
    cudaGetSymbolAddress((void**)&w116, g_wfc1);
    cudaGetSymbolAddress((void**)&w216, g_wfc2);
    cudaGetSymbolAddress((void**)&qq,   g_q);
    cudaGetSymbolAddress((void**)&kk,   g_k);
    cudaGetSymbolAddress((void**)&vv,   g_v);

    TMEncodeFn enc = nullptr;
    cudaDriverEntryPointQueryResult qres;
    cudaGetDriverEntryPointByVersion("cuTensorMapEncodeTiled", (void**)&enc, 12000,
                                     cudaEnableDefault, &qres);

    cudaFuncSetAttribute((const void*)gemm_tc<0>, cudaFuncAttributeMaxDynamicSharedMemorySize, SMEM_BYTES);
    cudaFuncSetAttribute((const void*)gemm_tc<1>, cudaFuncAttributeMaxDynamicSharedMemorySize, SMEM_BYTES);
    cudaFuncSetAttribute((const void*)gemm_tc<2>, cudaFuncAttributeMaxDynamicSharedMemorySize, SMEM_BYTES);
    cudaFuncSetAttribute((const void*)flash_mma,  cudaFuncAttributeMaxDynamicSharedMemorySize, FLASH_SMEM);

    CUtensorMap mA, mB;

    // 0+1) fused: convert all weights fp16 + ln1 -> a16
    fused_prep<<<ROWS + (N4_ALL + 255)/256, 256>>>(x, ln1w, ln1b, a16,
        wqkv, wproj, wfc1, wfc2, wq16, wp16, w116, w216);
    // 2) qkv GEMM -> scatter Q/K/V : [4096,3072], K=1024
    enc_map(enc, &mA, a16, ROWS, H_);
    enc_map(enc, &mB, wq16, H3, H_);
    launch_pdl(gemm_tc<0>, dim3(H3/128, ROWS/128), dim3(288), (size_t)SMEM_BYTES,
        mA, mB, bqkv, (const float*)nullptr, (float*)nullptr, (__half*)nullptr,
        qq, kk, vv, (int)H3, (int)(H_/64));
    // 3) flash attention -> a16
    launch_pdl(flash_mma, dim3(S_/128, BHN), dim3(256), (size_t)FLASH_SMEM,
        (const __half*)qq, (const __half*)kk, (const __half*)vv, a16);
    // 4) x1 = x + attn @ wproj^T + b : [4096,1024], K=1024
    enc_map(enc, &mB, wp16, H_, H_);
    launch_pdl(gemm_tc<2>, dim3(H_/128, ROWS/128), dim3(288), (size_t)SMEM_BYTES,
        mA, mB, bproj, x, x1, (__half*)nullptr,
        (__half*)nullptr, (__half*)nullptr, (__half*)nullptr, (int)H_, (int)(H_/64));
    // 5) ln2 -> a16
    launch_pdl(ln_h, dim3(ROWS), dim3(256), (size_t)0, (const float*)x1, ln2w, ln2b, a16);
    // 6) mid = gelu(ln2 @ wfc1^T + b) -> m16 : [4096,4096], K=1024
    enc_map(enc, &mB, w116, H4, H_);
    launch_pdl(gemm_tc<1>, dim3(H4/128, ROWS/128), dim3(288), (size_t)SMEM_BYTES,
        mA, mB, bfc1, (const float*)nullptr, (float*)nullptr, m16,
        (__half*)nullptr, (__half*)nullptr, (__half*)nullptr, (int)H4, (int)(H_/64));
    // 7) out = x1 + mid @ wfc2^T + b : [4096,1024], K=4096
    enc_map(enc, &mA, m16, ROWS, H4);
    enc_map(enc, &mB, w216, H_, H4);
    launch_pdl(gemm_tc<2>, dim3(H_/128, ROWS/128), dim3(288), (size_t)SMEM_BYTES,
        mA, mB, bfc2, (const float*)x1, out, (__half*)nullptr,
        (__half*)nullptr, (__half*)nullptr, (__half*)nullptr, (int)H_, (int)(H4/64));
}